// round 9
// baseline (speedup 1.0000x reference)
#include <cuda_runtime.h>
#include <cuda_bf16.h>
#include <math.h>
#include <stdint.h>

// ---------------------------------------------------------------------------
// Problem constants
// ---------------------------------------------------------------------------
#define N_   50000
#define E_   400000
// ND=128, ED=64, HID=128, GIN=258 (padded to 272), CIN=320

// ---------------------------------------------------------------------------
// Static device scratch
// ---------------------------------------------------------------------------
__device__ __align__(16) int   g_deg_out[N_];
__device__ __align__(16) int   g_deg_in[N_];
__device__ __align__(16) float g_xout[(size_t)N_*128];
__device__ __align__(16) float g_xin [(size_t)N_*128];
__device__ __align__(16) float g_loop[(size_t)N_*64];
__device__ __align__(16) float g_xi  [(size_t)N_*272];   // zero-padded 258..271
__device__ __align__(16) float g_x1  [(size_t)N_*512];   // xl1 | xr1
__device__ __align__(16) float g_den1[N_*2];
__device__ __align__(16) float g_osum1[(size_t)N_*256];
__device__ __align__(16) float g_h1  [(size_t)N_*128];
__device__ __align__(16) float g_x2  [(size_t)N_*256];   // xl2 | xr2
__device__ __align__(16) float g_den2[N_];
__device__ __align__(16) float g_osum2[(size_t)N_*128];
__device__ __align__(16) float g_h2  [(size_t)N_*128];
__device__ __align__(16) float g_AB  [(size_t)N_*256];   // Asrc | Bdst

// packed weights: [n][kpad/2] uint32 (bf16x2 pairs along k)
__device__ __align__(16) uint32_t wp_W1h[512*136], wp_W1l[512*136];   // g1wl|g1wr, kpad=272
__device__ __align__(16) uint32_t wp_Weh[512*32],  wp_Wel[512*32];    // g1we|g2we|c1w_e, kpad=64
__device__ __align__(16) uint32_t wp_W2h[256*64],  wp_W2l[256*64];    // g2wl|g2wr, kpad=128
__device__ __align__(16) uint32_t wp_ABh[256*64],  wp_ABl[256*64];    // c1w_a|c1w_b, kpad=128
__device__ __align__(16) uint32_t wp_Ebh[128*32],  wp_Ebl[128*32];    // epw, kpad=64
__device__ __align__(16) uint32_t wp_C2h[64*64],   wp_C2l[64*64];     // c2w, kpad=128

// ---------------------------------------------------------------------------
// Helpers
// ---------------------------------------------------------------------------
__device__ __forceinline__ void red4(float* addr, float4 v) {
    asm volatile("red.global.add.v4.f32 [%0], {%1,%2,%3,%4};"
                 :: "l"(addr), "f"(v.x), "f"(v.y), "f"(v.z), "f"(v.w) : "memory");
}
__device__ __forceinline__ void red2(float* addr, float a, float b) {
    asm volatile("red.global.add.v2.f32 [%0], {%1,%2};"
                 :: "l"(addr), "f"(a), "f"(b) : "memory");
}

__device__ __forceinline__ void mma_bf16(float* c, const uint32_t* a, const uint32_t* b) {
    asm volatile(
        "mma.sync.aligned.m16n8k16.row.col.f32.bf16.bf16.f32 "
        "{%0,%1,%2,%3}, {%4,%5,%6,%7}, {%8,%9}, {%0,%1,%2,%3};"
        : "+f"(c[0]), "+f"(c[1]), "+f"(c[2]), "+f"(c[3])
        : "r"(a[0]), "r"(a[1]), "r"(a[2]), "r"(a[3]), "r"(b[0]), "r"(b[1]));
}

__device__ __forceinline__ uint32_t pack_bf(__nv_bfloat16 a, __nv_bfloat16 b) {
    __nv_bfloat162 t; t.x = a; t.y = b;
    uint32_t r; memcpy(&r, &t, 4); return r;
}

__device__ __forceinline__ void split2(float x, float y, uint32_t& hi, uint32_t& lo) {
    __nv_bfloat16 hx = __float2bfloat16_rn(x);
    __nv_bfloat16 hy = __float2bfloat16_rn(y);
    __nv_bfloat16 lx = __float2bfloat16_rn(x - __bfloat162float(hx));
    __nv_bfloat16 ly = __float2bfloat16_rn(y - __bfloat162float(hy));
    hi = pack_bf(hx, hy);
    lo = pack_bf(lx, ly);
}

// smem layout: s[row][k2] with k2 XOR-swizzled by (row&7); stride 8 uint32.
__device__ __forceinline__ uint32_t lds_sw(const uint32_t* s, int r, int k2) {
    return s[r * 8 + (k2 ^ (r & 7))];
}
__device__ __forceinline__ void sts_pair(uint32_t* s, int m, int k2, uint32_t u0, uint32_t u1) {
    int x = m & 7;
    int p0 = k2 ^ x;
    if (x & 1) { uint32_t t = u0; u0 = u1; u1 = t; }
    *(uint2*)&s[m * 8 + (p0 & ~1)] = make_uint2(u0, u1);
}

// ---------------------------------------------------------------------------
// Tensor-core GEMM, bf16x3 compensated, packed weights, pipelined.
// EPI: 0 = fp32 store; 2 = +bias, relu, red.v2 scatter to g_xout/g_xin.
// ---------------------------------------------------------------------------
template<int EPI>
__global__ __launch_bounds__(256, 2)
void gemm_pk(const float* __restrict__ A,
             const uint32_t* __restrict__ Wh, const uint32_t* __restrict__ Wl,
             const float* __restrict__ bias, float* __restrict__ C,
             int M, int N, int K, int lda, int ldc,
             const int* __restrict__ src, const int* __restrict__ dst)
{
    constexpr int BM = 128, BN = 128;
    __shared__ __align__(16) uint32_t sAh[BM*8], sAl[BM*8], sBh[BN*8], sBl[BN*8];

    const int bm = blockIdx.y * BM, bn = blockIdx.x * BN;
    const int tid = threadIdx.x, wid = tid >> 5, lane = tid & 31;
    const int wm = (wid & 3) * 32, wn = (wid >> 2) * 64;
    const int g = lane >> 2, tig = lane & 3;
    const int wstride = K >> 1;

    const int am0 = tid >> 2, af = tid & 3;
    const int am1 = 64 + (tid >> 2);
    const int wns = tid >> 1, wpart = tid & 1;

    float acc[2][8][4] = {};
    float4 pa0, pa1; uint4 pwh, pwl;

    {   // prologue: tile 0
        int gm0 = bm + am0, gm1 = bm + am1;
        pa0 = (gm0 < M) ? *(const float4*)&A[(size_t)gm0 * lda + af * 4] : make_float4(0,0,0,0);
        pa1 = (gm1 < M) ? *(const float4*)&A[(size_t)gm1 * lda + af * 4] : make_float4(0,0,0,0);
        size_t off = (size_t)(bn + wns) * wstride + wpart * 4;
        pwh = *(const uint4*)&Wh[off];
        pwl = *(const uint4*)&Wl[off];
    }

    const int KT = K >> 4;
    for (int kt = 0; kt < KT; kt++) {
        {
            uint32_t h0, l0, h1, l1;
            split2(pa0.x, pa0.y, h0, l0);
            split2(pa0.z, pa0.w, h1, l1);
            sts_pair(sAh, am0, af * 2, h0, h1);
            sts_pair(sAl, am0, af * 2, l0, l1);
            split2(pa1.x, pa1.y, h0, l0);
            split2(pa1.z, pa1.w, h1, l1);
            sts_pair(sAh, am1, af * 2, h0, h1);
            sts_pair(sAl, am1, af * 2, l0, l1);
            sts_pair(sBh, wns, wpart * 4 + 0, pwh.x, pwh.y);
            sts_pair(sBh, wns, wpart * 4 + 2, pwh.z, pwh.w);
            sts_pair(sBl, wns, wpart * 4 + 0, pwl.x, pwl.y);
            sts_pair(sBl, wns, wpart * 4 + 2, pwl.z, pwl.w);
        }
        __syncthreads();

        if (kt + 1 < KT) {
            int k0 = (kt + 1) * 16;
            int gm0 = bm + am0, gm1 = bm + am1;
            pa0 = (gm0 < M) ? *(const float4*)&A[(size_t)gm0 * lda + k0 + af * 4] : make_float4(0,0,0,0);
            pa1 = (gm1 < M) ? *(const float4*)&A[(size_t)gm1 * lda + k0 + af * 4] : make_float4(0,0,0,0);
            size_t off = (size_t)(bn + wns) * wstride + (k0 >> 1) + wpart * 4;
            pwh = *(const uint4*)&Wh[off];
            pwl = *(const uint4*)&Wl[off];
        }

        uint32_t ah[2][4], al[2][4];
        #pragma unroll
        for (int mt = 0; mt < 2; mt++) {
            int r0 = wm + mt * 16 + g;
            ah[mt][0] = lds_sw(sAh, r0,     tig);
            ah[mt][1] = lds_sw(sAh, r0 + 8, tig);
            ah[mt][2] = lds_sw(sAh, r0,     tig + 4);
            ah[mt][3] = lds_sw(sAh, r0 + 8, tig + 4);
            al[mt][0] = lds_sw(sAl, r0,     tig);
            al[mt][1] = lds_sw(sAl, r0 + 8, tig);
            al[mt][2] = lds_sw(sAl, r0,     tig + 4);
            al[mt][3] = lds_sw(sAl, r0 + 8, tig + 4);
        }
        #pragma unroll
        for (int nt = 0; nt < 8; nt++) {
            int n = wn + nt * 8 + g;
            uint32_t bh[2], bl[2];
            bh[0] = lds_sw(sBh, n, tig);
            bh[1] = lds_sw(sBh, n, tig + 4);
            bl[0] = lds_sw(sBl, n, tig);
            bl[1] = lds_sw(sBl, n, tig + 4);
            #pragma unroll
            for (int mt = 0; mt < 2; mt++) {
                mma_bf16(acc[mt][nt], ah[mt], bh);
                mma_bf16(acc[mt][nt], al[mt], bh);
                mma_bf16(acc[mt][nt], ah[mt], bl);
            }
        }
        __syncthreads();
    }

    #pragma unroll
    for (int mt = 0; mt < 2; mt++) {
        #pragma unroll
        for (int half = 0; half < 2; half++) {
            int r = bm + wm + mt * 16 + g + half * 8;
            if (r >= M) continue;
            int s = 0, d = 0;
            if (EPI == 2) { s = src[r]; d = dst[r]; }
            #pragma unroll
            for (int nt = 0; nt < 8; nt++) {
                int col0 = bn + wn + nt * 8 + tig * 2;
                float v0 = acc[mt][nt][half * 2 + 0];
                float v1 = acc[mt][nt][half * 2 + 1];
                if (EPI == 2) {
                    v0 = fmaxf(v0 + bias[col0], 0.f);
                    v1 = fmaxf(v1 + bias[col0 + 1], 0.f);
                    red2(&g_xout[(size_t)s * 128 + col0], v0, v1);
                    red2(&g_xin [(size_t)d * 128 + col0], v0, v1);
                } else {
                    *(float2*)&C[(size_t)r * ldc + col0] = make_float2(v0, v1);
                }
            }
        }
    }
}

// ---------------------------------------------------------------------------
// Pack weights into bf16 hi/lo uint32, n-major [n][kpad/2]. One launch.
// ---------------------------------------------------------------------------
__global__ void k_pack(const float* __restrict__ g1wl, const float* __restrict__ g1wr,
                       const float* __restrict__ g1we, const float* __restrict__ g2we,
                       const float* __restrict__ c1w,  const float* __restrict__ g2wl,
                       const float* __restrict__ g2wr, const float* __restrict__ epw,
                       const float* __restrict__ c2w)
{
    const float* W; int K, N, n0, kpad; uint32_t *dh, *dl;
    switch (blockIdx.y) {
        case 0: W = g1wl;           K = 258; N = 256; n0 = 0;   kpad = 272; dh = wp_W1h; dl = wp_W1l; break;
        case 1: W = g1wr;           K = 258; N = 256; n0 = 256; kpad = 272; dh = wp_W1h; dl = wp_W1l; break;
        case 2: W = g1we;           K = 64;  N = 256; n0 = 0;   kpad = 64;  dh = wp_Weh; dl = wp_Wel; break;
        case 3: W = g2we;           K = 64;  N = 128; n0 = 256; kpad = 64;  dh = wp_Weh; dl = wp_Wel; break;
        case 4: W = c1w + 256*128;  K = 64;  N = 128; n0 = 384; kpad = 64;  dh = wp_Weh; dl = wp_Wel; break;
        case 5: W = g2wl;           K = 128; N = 128; n0 = 0;   kpad = 128; dh = wp_W2h; dl = wp_W2l; break;
        case 6: W = g2wr;           K = 128; N = 128; n0 = 128; kpad = 128; dh = wp_W2h; dl = wp_W2l; break;
        case 7: W = c1w;            K = 128; N = 128; n0 = 0;   kpad = 128; dh = wp_ABh; dl = wp_ABl; break;
        case 8: W = c1w + 128*128;  K = 128; N = 128; n0 = 128; kpad = 128; dh = wp_ABh; dl = wp_ABl; break;
        case 9: W = epw;            K = 64;  N = 128; n0 = 0;   kpad = 64;  dh = wp_Ebh; dl = wp_Ebl; break;
        default: W = c2w;           K = 128; N = 64;  n0 = 0;   kpad = 128; dh = wp_C2h; dl = wp_C2l; break;
    }
    int kh = kpad >> 1;
    int total = N * kh;
    for (int i = blockIdx.x * blockDim.x + threadIdx.x; i < total; i += gridDim.x * blockDim.x) {
        int n = i / kh, k2 = i - n * kh, k = k2 * 2;
        float v0 = (k     < K) ? W[(size_t)k * N + n]       : 0.f;
        float v1 = (k + 1 < K) ? W[(size_t)(k + 1) * N + n] : 0.f;
        uint32_t hi, lo; split2(v0, v1, hi, lo);
        dh[(size_t)(n0 + n) * kh + k2] = hi;
        dl[(size_t)(n0 + n) * kh + k2] = lo;
    }
}

// ---------------------------------------------------------------------------
// Degrees + loop_attr sum. 1 warp / edge.
// ---------------------------------------------------------------------------
__global__ void k_deg_loop(const int* __restrict__ src, const int* __restrict__ dst,
                           const float* __restrict__ ea) {
    int warp = (blockIdx.x * 256 + threadIdx.x) >> 5;
    int lane = threadIdx.x & 31;
    if (warp >= E_) return;
    int s = src[warp], d = dst[warp];
    if (lane == 0) atomicAdd(&g_deg_out[s], 1);
    if (lane == 1) atomicAdd(&g_deg_in[d], 1);
    if (lane < 16) {
        float4 a = reinterpret_cast<const float4*>(ea + (size_t)warp * 64)[lane];
        red4(&g_loop[(size_t)d * 64 + lane * 4], a);
    }
}

// ---------------------------------------------------------------------------
// Build xi (stride 272); finalize loop_attr. 1 warp / node, float4 I/O.
// ---------------------------------------------------------------------------
__global__ void k_build_xi(const float* __restrict__ node_stats) {
    int warp = (blockIdx.x * 256 + threadIdx.x) >> 5;
    int lane = threadIdx.x & 31;
    if (warp >= N_) return;
    float io = 1.f / fmaxf((float)g_deg_out[warp], 1.f);
    float ii = 1.f / fmaxf((float)g_deg_in[warp], 1.f);
    float4 o = ((const float4*)(g_xout + (size_t)warp * 128))[lane];
    float4 i4 = ((const float4*)(g_xin  + (size_t)warp * 128))[lane];
    o.x *= io; o.y *= io; o.z *= io; o.w *= io;
    i4.x *= ii; i4.y *= ii; i4.z *= ii; i4.w *= ii;
    float* xi = g_xi + (size_t)warp * 272;
    ((float4*)xi)[lane] = o;
    ((float4*)(xi + 128))[lane] = i4;
    if (lane < 4) {
        float4 p = make_float4(0.f, 0.f, 0.f, 0.f);
        if (lane == 0) { p.x = node_stats[(size_t)warp * 2]; p.y = node_stats[(size_t)warp * 2 + 1]; }
        ((float4*)(xi + 256))[lane] = p;
    }
    if (lane < 16) {
        float4 l4 = ((float4*)(g_loop + (size_t)warp * 64))[lane];
        l4.x *= ii; l4.y *= ii; l4.z *= ii; l4.w *= ii;
        ((float4*)(g_loop + (size_t)warp * 64))[lane] = l4;
    }
}

// ---------------------------------------------------------------------------
// Fused ew-GEMM + GATv2 attention.
// Stage 1: T[128, CH] = A[bm:bm+128, 0:64] @ W (bf16x3 MMA, B-frags from
//          packed gmem) -> fp32 smem.
// Stage 2: per-edge logit (xl[s]+xr[d]+T from smem), exp (no max shift),
//          den atomic + weighted red4 scatter of xl.
// LOOP=false: rows are edges (src/dst gathered). LOOP=true: rows are nodes
// (self loops, s=d=row; A = loop_attr). H=2: 512 thr; H=1: 256 thr.
// ---------------------------------------------------------------------------
template<int H, bool LOOP>
__global__ __launch_bounds__(H * 256, 1)
void k_attn_fused(const float* __restrict__ A,
                  const uint32_t* __restrict__ Wh, const uint32_t* __restrict__ Wl,
                  const float* __restrict__ x, int xstr, int xroff,
                  const float* __restrict__ att,
                  const int* __restrict__ src, const int* __restrict__ dst,
                  float* __restrict__ den, float* __restrict__ osum, int M)
{
    constexpr int CH = H * 128;
    constexpr int NT = H * 256;
    constexpr int NW = NT / 32;
    constexpr int EPW = 128 / NW;

    extern __shared__ __align__(16) char smem_raw[];
    float*    sT   = (float*)smem_raw;            // 128*CH fp32
    uint32_t* sAh  = (uint32_t*)(sT + 128 * CH);  // 128*8
    uint32_t* sAl  = sAh + 128 * 8;               // 128*8
    float*    satt = (float*)(sAl + 128 * 8);     // CH
    int*      ssrc = (int*)(satt + CH);           // 128
    int*      sdst = ssrc + 128;                  // 128

    const int bm = blockIdx.x * 128;
    const int tid = threadIdx.x, wid = tid >> 5, lane = tid & 31;
    const int wm = (wid & 3) * 32;
    const int wn = (wid >> 2) * 64;
    const int g = lane >> 2, tig = lane & 3;

    if (tid < CH) satt[tid] = att[tid];
    if (!LOOP && tid < 128) { ssrc[tid] = src[bm + tid]; sdst[tid] = dst[bm + tid]; }

    // ---- stage 1: MMA ----
    float acc[2][8][4] = {};
    #pragma unroll
    for (int kt = 0; kt < 4; kt++) {
        for (int i = tid; i < 512; i += NT) {
            int m = i >> 2, f = i & 3;
            int gm = bm + m;
            float4 a = (gm < M) ? *(const float4*)&A[(size_t)gm * 64 + kt * 16 + f * 4]
                                : make_float4(0, 0, 0, 0);
            uint32_t h0, l0, h1, l1;
            split2(a.x, a.y, h0, l0); split2(a.z, a.w, h1, l1);
            sts_pair(sAh, m, f * 2, h0, h1);
            sts_pair(sAl, m, f * 2, l0, l1);
        }
        __syncthreads();

        uint32_t ah[2][4], al[2][4];
        #pragma unroll
        for (int mt = 0; mt < 2; mt++) {
            int r0 = wm + mt * 16 + g;
            ah[mt][0] = lds_sw(sAh, r0,     tig);
            ah[mt][1] = lds_sw(sAh, r0 + 8, tig);
            ah[mt][2] = lds_sw(sAh, r0,     tig + 4);
            ah[mt][3] = lds_sw(sAh, r0 + 8, tig + 4);
            al[mt][0] = lds_sw(sAl, r0,     tig);
            al[mt][1] = lds_sw(sAl, r0 + 8, tig);
            al[mt][2] = lds_sw(sAl, r0,     tig + 4);
            al[mt][3] = lds_sw(sAl, r0 + 8, tig + 4);
        }
        #pragma unroll
        for (int nt = 0; nt < 8; nt++) {
            int n = wn + nt * 8 + g;
            uint32_t bh[2], bl[2];
            bh[0] = __ldg(&Wh[n * 32 + kt * 8 + tig]);
            bh[1] = __ldg(&Wh[n * 32 + kt * 8 + tig + 4]);
            bl[0] = __ldg(&Wl[n * 32 + kt * 8 + tig]);
            bl[1] = __ldg(&Wl[n * 32 + kt * 8 + tig + 4]);
            #pragma unroll
            for (int mt = 0; mt < 2; mt++) {
                mma_bf16(acc[mt][nt], ah[mt], bh);
                mma_bf16(acc[mt][nt], al[mt], bh);
                mma_bf16(acc[mt][nt], ah[mt], bl);
            }
        }
        __syncthreads();
    }

    // ---- stage-1 epilogue: park T in fp32 smem ----
    #pragma unroll
    for (int mt = 0; mt < 2; mt++) {
        #pragma unroll
        for (int half = 0; half < 2; half++) {
            int r = wm + mt * 16 + g + half * 8;
            #pragma unroll
            for (int nt = 0; nt < 8; nt++) {
                int col0 = wn + nt * 8 + tig * 2;
                *(float2*)&sT[r * CH + col0] =
                    make_float2(acc[mt][nt][half * 2 + 0], acc[mt][nt][half * 2 + 1]);
            }
        }
    }
    __syncthreads();

    // ---- stage 2: attention ----
    for (int i = 0; i < EPW; i++) {
        int e = wid * EPW + i;
        int ge = bm + e;
        if (LOOP && ge >= M) break;
        int s, d;
        if (LOOP) { s = ge; d = ge; }
        else      { s = ssrc[e]; d = sdst[e]; }
        const float* pl = x + (size_t)s * xstr;
        const float* pr = x + (size_t)d * xstr + xroff;
        const float* ew = sT + (size_t)e * CH;

        float4 xlv[H];
        float lg[H];
        #pragma unroll
        for (int h = 0; h < H; h++) {
            int off = h * 128 + lane * 4;
            float4 l4 = *(const float4*)&pl[off];
            float4 r4 = *(const float4*)&pr[off];
            float4 e4 = *(const float4*)&ew[off];
            float4 a4 = *(const float4*)&satt[off];
            xlv[h] = l4;
            float v0 = l4.x + r4.x + e4.x; v0 = (v0 > 0.f) ? v0 : 0.2f * v0;
            float v1 = l4.y + r4.y + e4.y; v1 = (v1 > 0.f) ? v1 : 0.2f * v1;
            float v2 = l4.z + r4.z + e4.z; v2 = (v2 > 0.f) ? v2 : 0.2f * v2;
            float v3 = l4.w + r4.w + e4.w; v3 = (v3 > 0.f) ? v3 : 0.2f * v3;
            lg[h] = v0 * a4.x + v1 * a4.y + v2 * a4.z + v3 * a4.w;
        }
        #pragma unroll
        for (int h = 0; h < H; h++)
            #pragma unroll
            for (int o = 16; o > 0; o >>= 1)
                lg[h] += __shfl_xor_sync(0xffffffffu, lg[h], o);
        float a[H];
        #pragma unroll
        for (int h = 0; h < H; h++) a[h] = expf(lg[h]);
        if (lane == 0) {
            #pragma unroll
            for (int h = 0; h < H; h++) atomicAdd(&den[(size_t)d * H + h], a[h]);
        }
        #pragma unroll
        for (int h = 0; h < H; h++) {
            float4 v = xlv[h];
            v.x *= a[h]; v.y *= a[h]; v.z *= a[h]; v.w *= a[h];
            red4(&osum[((size_t)d * H + h) * 128 + lane * 4], v);
        }
    }
}

// ---------------------------------------------------------------------------
// Node finalize: head mean + bias, layernorm, elu. 1 warp / node.
// ---------------------------------------------------------------------------
template<int H>
__global__ void k_node(const float* __restrict__ osum, const float* __restrict__ den,
                       const float* __restrict__ bias,
                       const float* __restrict__ lng, const float* __restrict__ lnb,
                       float* __restrict__ out)
{
    int warp = (blockIdx.x * 256 + threadIdx.x) >> 5;
    int lane = threadIdx.x & 31;
    if (warp >= N_) return;
    int n = warp;
    float dinv[H];
    #pragma unroll
    for (int h = 0; h < H; h++)
        dinv[h] = 1.f / fmaxf(den[(size_t)n * H + h], 1e-16f);
    float v[4];
    float sum = 0.f;
    #pragma unroll
    for (int i = 0; i < 4; i++) {
        int c = i * 32 + lane;
        float o = 0.f;
        #pragma unroll
        for (int h = 0; h < H; h++)
            o += osum[((size_t)n * H + h) * 128 + c] * dinv[h];
        o = o * (1.f / H) + bias[c];
        v[i] = o;
        sum += o;
    }
    #pragma unroll
    for (int o = 16; o > 0; o >>= 1) sum += __shfl_xor_sync(0xffffffffu, sum, o);
    float mu = sum * (1.f / 128.f);
    float var = 0.f;
    #pragma unroll
    for (int i = 0; i < 4; i++) { float t = v[i] - mu; var += t * t; }
    #pragma unroll
    for (int o = 16; o > 0; o >>= 1) var += __shfl_xor_sync(0xffffffffu, var, o);
    var *= (1.f / 128.f);
    float rs = rsqrtf(var + 1e-5f);
    #pragma unroll
    for (int i = 0; i < 4; i++) {
        int c = i * 32 + lane;
        float hn = (v[i] - mu) * rs * lng[c] + lnb[c];
        hn = (hn > 0.f) ? hn : expm1f(hn);
        out[(size_t)n * 128 + c] = hn;
    }
}

// ---------------------------------------------------------------------------
// Fully fused classifier (two MMA stages, no Cea materialization).
// ---------------------------------------------------------------------------
__global__ __launch_bounds__(256, 2)
void k_classifier(const int* __restrict__ src, const int* __restrict__ dst,
                  const float* __restrict__ ea,
                  const uint32_t* __restrict__ W1h, const uint32_t* __restrict__ W1l,
                  const uint32_t* __restrict__ W2h, const uint32_t* __restrict__ W2l,
                  const float* __restrict__ c1b, const float* __restrict__ c2b,
                  const float* __restrict__ c3w, const float* __restrict__ c3b,
                  float* __restrict__ out)
{
    extern __shared__ __align__(16) char smem_raw[];
    uint32_t* sAh = (uint32_t*)smem_raw;        // 128*8
    uint32_t* sAl = sAh + 128*8;                // 128*8
    uint32_t* s2h = sAl + 128*8;                // 128*64
    uint32_t* s2l = s2h + 128*64;               // 128*64
    int*   ssrc   = (int*)(s2l + 128*64);       // 128
    int*   sdst   = ssrc + 128;                 // 128
    float* rowsum = (float*)(sdst + 128);       // 128

    const int bm = blockIdx.x * 128;
    const int tid = threadIdx.x, wid = tid >> 5, lane = tid & 31;
    const int wm = (wid & 3) * 32;
    const int wn = (wid >> 2) * 64;
    const int wn2 = (wid >> 2) * 32;
    const int g = lane >> 2, tig = lane & 3;
    const int am0 = tid >> 2, af = tid & 3;
    const int am1 = 64 + (tid >> 2);

    if (tid < 128) {
        ssrc[tid] = src[bm + tid];
        sdst[tid] = dst[bm + tid];
        rowsum[tid] = 0.f;
    }

    // stage 1: T = ea @ c1w_e
    float acc1[2][8][4] = {};
    for (int kt = 0; kt < 4; kt++) {
        int k0 = kt * 16;
        {
            float4 a0 = *(const float4*)&ea[(size_t)(bm + am0) * 64 + k0 + af * 4];
            float4 a1 = *(const float4*)&ea[(size_t)(bm + am1) * 64 + k0 + af * 4];
            uint32_t h0, l0, h1, l1;
            split2(a0.x, a0.y, h0, l0); split2(a0.z, a0.w, h1, l1);
            sts_pair(sAh, am0, af * 2, h0, h1); sts_pair(sAl, am0, af * 2, l0, l1);
            split2(a1.x, a1.y, h0, l0); split2(a1.z, a1.w, h1, l1);
            sts_pair(sAh, am1, af * 2, h0, h1); sts_pair(sAl, am1, af * 2, l0, l1);
        }
        __syncthreads();

        uint32_t ah[2][4], al[2][4];
        #pragma unroll
        for (int mt = 0; mt < 2; mt++) {
            int r0 = wm + mt * 16 + g;
            ah[mt][0] = lds_sw(sAh, r0,     tig);
            ah[mt][1] = lds_sw(sAh, r0 + 8, tig);
            ah[mt][2] = lds_sw(sAh, r0,     tig + 4);
            ah[mt][3] = lds_sw(sAh, r0 + 8, tig + 4);
            al[mt][0] = lds_sw(sAl, r0,     tig);
            al[mt][1] = lds_sw(sAl, r0 + 8, tig);
            al[mt][2] = lds_sw(sAl, r0,     tig + 4);
            al[mt][3] = lds_sw(sAl, r0 + 8, tig + 4);
        }
        #pragma unroll
        for (int nt = 0; nt < 8; nt++) {
            int n = wn + nt * 8 + g;
            uint32_t bh[2], bl[2];
            bh[0] = __ldg(&W1h[n * 32 + kt * 8 + tig]);
            bh[1] = __ldg(&W1h[n * 32 + kt * 8 + tig + 4]);
            bl[0] = __ldg(&W1l[n * 32 + kt * 8 + tig]);
            bl[1] = __ldg(&W1l[n * 32 + kt * 8 + tig + 4]);
            #pragma unroll
            for (int mt = 0; mt < 2; mt++) {
                mma_bf16(acc1[mt][nt], ah[mt], bh);
                mma_bf16(acc1[mt][nt], al[mt], bh);
                mma_bf16(acc1[mt][nt], ah[mt], bl);
            }
        }
        __syncthreads();
    }

    // epilogue 1
    #pragma unroll
    for (int mt = 0; mt < 2; mt++) {
        #pragma unroll
        for (int half = 0; half < 2; half++) {
            int r = wm + mt * 16 + g + half * 8;
            int s = ssrc[r], d = sdst[r];
            #pragma unroll
            for (int nt = 0; nt < 8; nt++) {
                int col0 = wn + nt * 8 + tig * 2;
                float v0 = acc1[mt][nt][half * 2 + 0]
                         + g_AB[(size_t)s * 256 + col0]
                         + g_AB[(size_t)d * 256 + 128 + col0] + c1b[col0];
                float v1 = acc1[mt][nt][half * 2 + 1]
                         + g_AB[(size_t)s * 256 + col0 + 1]
                         + g_AB[(size_t)d * 256 + 128 + col0 + 1] + c1b[col0 + 1];
                v0 = fmaxf(v0, 0.f); v1 = fmaxf(v1, 0.f);
                uint32_t hi, lo; split2(v0, v1, hi, lo);
                int k2 = col0 >> 1;
                int sw = k2 ^ ((r & 7) << 3);
                s2h[r * 64 + sw] = hi;
                s2l[r * 64 + sw] = lo;
            }
        }
    }
    __syncthreads();

    // stage 2: T @ c2w
    float acc2[2][4][4] = {};
    #pragma unroll
    for (int kt2 = 0; kt2 < 8; kt2++) {
        uint32_t ah[2][4], al[2][4];
        #pragma unroll
        for (int mt = 0; mt < 2; mt++) {
            int r0 = wm + mt * 16 + g;
            int r1 = r0 + 8;
            int x0 = (r0 & 7) << 3, x1 = (r1 & 7) << 3;
            ah[mt][0] = s2h[r0 * 64 + ((kt2 * 8 + tig)     ^ x0)];
            ah[mt][1] = s2h[r1 * 64 + ((kt2 * 8 + tig)     ^ x1)];
            ah[mt][2] = s2h[r0 * 64 + ((kt2 * 8 + tig + 4) ^ x0)];
            ah[mt][3] = s2h[r1 * 64 + ((kt2 * 8 + tig + 4) ^ x1)];
            al[mt][0] = s2l[r0 * 64 + ((kt2 * 8 + tig)     ^ x0)];
            al[mt][1] = s2l[r1 * 64 + ((kt2 * 8 + tig)     ^ x1)];
            al[mt][2] = s2l[r0 * 64 + ((kt2 * 8 + tig + 4) ^ x0)];
            al[mt][3] = s2l[r1 * 64 + ((kt2 * 8 + tig + 4) ^ x1)];
        }
        #pragma unroll
        for (int nt = 0; nt < 4; nt++) {
            int n = wn2 + nt * 8 + g;
            uint32_t bh[2], bl[2];
            bh[0] = __ldg(&W2h[n * 64 + kt2 * 8 + tig]);
            bh[1] = __ldg(&W2h[n * 64 + kt2 * 8 + tig + 4]);
            bl[0] = __ldg(&W2l[n * 64 + kt2 * 8 + tig]);
            bl[1] = __ldg(&W2l[n * 64 + kt2 * 8 + tig + 4]);
            #pragma unroll
            for (int mt = 0; mt < 2; mt++) {
                mma_bf16(acc2[mt][nt], ah[mt], bh);
                mma_bf16(acc2[mt][nt], al[mt], bh);
                mma_bf16(acc2[mt][nt], ah[mt], bl);
            }
        }
    }

    // epilogue 2
    #pragma unroll
    for (int mt = 0; mt < 2; mt++) {
        #pragma unroll
        for (int half = 0; half < 2; half++) {
            int r = wm + mt * 16 + g + half * 8;
            float p = 0.f;
            #pragma unroll
            for (int nt = 0; nt < 4; nt++) {
                int col = wn2 + nt * 8 + tig * 2;
                float t0 = fmaxf(acc2[mt][nt][half * 2 + 0] + c2b[col], 0.f);
                float t1 = fmaxf(acc2[mt][nt][half * 2 + 1] + c2b[col + 1], 0.f);
                p += t0 * c3w[col] + t1 * c3w[col + 1];
            }
            atomicAdd(&rowsum[r], p);
        }
    }
    __syncthreads();
    if (tid < 128) out[bm + tid] = rowsum[tid] + c3b[0];
}

// ---------------------------------------------------------------------------
// Host launch
// ---------------------------------------------------------------------------
static void* sym(const void* s) { void* p = nullptr; cudaGetSymbolAddress(&p, s); return p; }

static inline dim3 ggrid(int M, int N) { return dim3((N + 127) / 128, (M + 127) / 128); }

#define SMEM_CLS ((128*8*2 + 128*64*2) * 4 + 128*4*2 + 128*4)
#define SMEM_AF2 (128*256*4 + 128*8*4*2 + 256*4 + 256*4)
#define SMEM_AF1 (128*128*4 + 128*8*4*2 + 128*4 + 256*4)

extern "C" void kernel_launch(void* const* d_in, const int* in_sizes, int n_in,
                              void* d_out, int out_size)
{
    const float* node_stats = (const float*)d_in[1];
    const int*   edge_index = (const int*)  d_in[2];
    const float* edge_attr  = (const float*)d_in[3];
    const float* epw  = (const float*)d_in[4];
    const float* epb  = (const float*)d_in[5];
    const float* g1wl = (const float*)d_in[6];
    const float* g1wr = (const float*)d_in[7];
    const float* g1we = (const float*)d_in[8];
    const float* g1att= (const float*)d_in[9];
    const float* g1b  = (const float*)d_in[10];
    const float* n1g  = (const float*)d_in[11];
    const float* n1b  = (const float*)d_in[12];
    const float* g2wl = (const float*)d_in[13];
    const float* g2wr = (const float*)d_in[14];
    const float* g2we = (const float*)d_in[15];
    const float* g2att= (const float*)d_in[16];
    const float* g2b  = (const float*)d_in[17];
    const float* n2g  = (const float*)d_in[18];
    const float* n2b  = (const float*)d_in[19];
    const float* c1w  = (const float*)d_in[20];
    const float* c1b  = (const float*)d_in[21];
    const float* c2w  = (const float*)d_in[22];
    const float* c2b  = (const float*)d_in[23];
    const float* c3w  = (const float*)d_in[24];
    const float* c3b  = (const float*)d_in[25];

    const int* src = edge_index;
    const int* dst = edge_index + E_;
    float* out = (float*)d_out;

    float* p_xi   = (float*)sym(g_xi);
    float* p_loop = (float*)sym(g_loop);
    float* p_x1   = (float*)sym(g_x1);
    float* p_den1 = (float*)sym(g_den1);
    float* p_os1  = (float*)sym(g_osum1);
    float* p_h1   = (float*)sym(g_h1);
    float* p_x2   = (float*)sym(g_x2);
    float* p_den2 = (float*)sym(g_den2);
    float* p_os2  = (float*)sym(g_osum2);
    float* p_h2   = (float*)sym(g_h2);
    float* p_AB   = (float*)sym(g_AB);

    const uint32_t* p_W1h = (const uint32_t*)sym(wp_W1h);
    const uint32_t* p_W1l = (const uint32_t*)sym(wp_W1l);
    const uint32_t* p_Weh = (const uint32_t*)sym(wp_Weh);
    const uint32_t* p_Wel = (const uint32_t*)sym(wp_Wel);
    const uint32_t* p_W2h = (const uint32_t*)sym(wp_W2h);
    const uint32_t* p_W2l = (const uint32_t*)sym(wp_W2l);
    const uint32_t* p_ABh = (const uint32_t*)sym(wp_ABh);
    const uint32_t* p_ABl = (const uint32_t*)sym(wp_ABl);
    const uint32_t* p_Ebh = (const uint32_t*)sym(wp_Ebh);
    const uint32_t* p_Ebl = (const uint32_t*)sym(wp_Ebl);
    const uint32_t* p_C2h = (const uint32_t*)sym(wp_C2h);
    const uint32_t* p_C2l = (const uint32_t*)sym(wp_C2l);

    static bool attr_set = false;
    if (!attr_set) {
        cudaFuncSetAttribute(k_classifier, cudaFuncAttributeMaxDynamicSharedMemorySize, SMEM_CLS);
        cudaFuncSetAttribute(k_attn_fused<2, false>, cudaFuncAttributeMaxDynamicSharedMemorySize, SMEM_AF2);
        cudaFuncSetAttribute(k_attn_fused<2, true>,  cudaFuncAttributeMaxDynamicSharedMemorySize, SMEM_AF2);
        cudaFuncSetAttribute(k_attn_fused<1, false>, cudaFuncAttributeMaxDynamicSharedMemorySize, SMEM_AF1);
        cudaFuncSetAttribute(k_attn_fused<1, true>,  cudaFuncAttributeMaxDynamicSharedMemorySize, SMEM_AF1);
        attr_set = true;
    }

    // ---- zero accumulators ----
    cudaMemsetAsync(sym(g_deg_out), 0, (size_t)N_ * 4);
    cudaMemsetAsync(sym(g_deg_in),  0, (size_t)N_ * 4);
    cudaMemsetAsync(sym(g_xout),    0, (size_t)N_ * 128 * 4);
    cudaMemsetAsync(sym(g_xin),     0, (size_t)N_ * 128 * 4);
    cudaMemsetAsync(p_loop,         0, (size_t)N_ * 64 * 4);
    cudaMemsetAsync(p_den1,         0, (size_t)N_ * 2 * 4);
    cudaMemsetAsync(p_os1,          0, (size_t)N_ * 256 * 4);
    cudaMemsetAsync(p_den2,         0, (size_t)N_ * 4);
    cudaMemsetAsync(p_os2,          0, (size_t)N_ * 128 * 4);

    // ---- weight packing ----
    k_pack<<<dim3(144, 11), 256>>>(g1wl, g1wr, g1we, g2we, c1w, g2wl, g2wr, epw, c2w);

    // ---- phase 1: degrees, loop sums, emb GEMM fused with scatter ----
    k_deg_loop<<<(E_ + 7) / 8, 256>>>(src, dst, edge_attr);
    gemm_pk<2><<<ggrid(E_, 128), 256>>>(edge_attr, p_Ebh, p_Ebl, epb, nullptr,
                                        E_, 128, 64, 64, 0, src, dst);
    k_build_xi<<<(N_ + 7) / 8, 256>>>(node_stats);

    // ---- GAT layer 1 (heads=2) ----
    gemm_pk<0><<<ggrid(N_, 512), 256>>>(p_xi, p_W1h, p_W1l, nullptr, p_x1,
                                        N_, 512, 272, 272, 512, nullptr, nullptr);
    k_attn_fused<2, false><<<E_ / 128, 512, SMEM_AF2>>>(
        edge_attr, p_Weh, p_Wel, p_x1, 512, 256, g1att, src, dst, p_den1, p_os1, E_);
    k_attn_fused<2, true><<<(N_ + 127) / 128, 512, SMEM_AF2>>>(
        p_loop, p_Weh, p_Wel, p_x1, 512, 256, g1att, nullptr, nullptr, p_den1, p_os1, N_);
    k_node<2><<<(N_ + 7) / 8, 256>>>(p_os1, p_den1, g1b, n1g, n1b, p_h1);

    // ---- GAT layer 2 (heads=1) ----
    gemm_pk<0><<<ggrid(N_, 256), 256>>>(p_h1, p_W2h, p_W2l, nullptr, p_x2,
                                        N_, 256, 128, 128, 256, nullptr, nullptr);
    k_attn_fused<1, false><<<E_ / 128, 256, SMEM_AF1>>>(
        edge_attr, p_Weh + 256 * 32, p_Wel + 256 * 32, p_x2, 256, 128,
        g2att, src, dst, p_den2, p_os2, E_);
    k_attn_fused<1, true><<<(N_ + 127) / 128, 256, SMEM_AF1>>>(
        p_loop, p_Weh + 256 * 32, p_Wel + 256 * 32, p_x2, 256, 128,
        g2att, nullptr, nullptr, p_den2, p_os2, N_);
    k_node<1><<<(N_ + 7) / 8, 256>>>(p_os2, p_den2, g2b, n2g, n2b, p_h2);

    // ---- classifier ----
    gemm_pk<0><<<ggrid(N_, 256), 256>>>(p_h2, p_ABh, p_ABl, nullptr, p_AB,
                                        N_, 256, 128, 128, 256, nullptr, nullptr);
    k_classifier<<<E_ / 128, 256, SMEM_CLS>>>(src, dst, edge_attr,
                                              p_Weh + 384 * 32, p_Wel + 384 * 32,
                                              p_C2h, p_C2l,
                                              c1b, c2b, c3w, c3b, out);
}

// round 10
// speedup vs baseline: 1.2133x; 1.2133x over previous
#include <cuda_runtime.h>
#include <cuda_bf16.h>
#include <math.h>
#include <stdint.h>

// ---------------------------------------------------------------------------
// Problem constants
// ---------------------------------------------------------------------------
#define N_   50000
#define E_   400000
// ND=128, ED=64, HID=128, GIN=258 (padded to 272), CIN=320

// ---------------------------------------------------------------------------
// Static device scratch
// ---------------------------------------------------------------------------
__device__ __align__(16) int   g_deg_out[N_];
__device__ __align__(16) int   g_deg_in[N_];
__device__ __align__(16) float g_xout[(size_t)N_*128];
__device__ __align__(16) float g_xin [(size_t)N_*128];
__device__ __align__(16) float g_loop[(size_t)N_*64];
__device__ __align__(16) float g_xi  [(size_t)N_*272];   // zero-padded 258..271
__device__ __align__(16) float g_x1  [(size_t)N_*512];   // xl1 | xr1
__device__ __align__(16) float g_ew  [(size_t)E_*384];   // ewE1(256) | ewE2(128)
__device__ __align__(16) float g_ewL [(size_t)N_*384];   // ewL1(256) | ewL2(128)
__device__ __align__(16) float g_den1[N_*2];
__device__ __align__(16) float g_osum1[(size_t)N_*256];
__device__ __align__(16) float g_h1  [(size_t)N_*128];
__device__ __align__(16) float g_x2  [(size_t)N_*256];   // xl2 | xr2
__device__ __align__(16) float g_den2[N_];
__device__ __align__(16) float g_osum2[(size_t)N_*128];
__device__ __align__(16) float g_h2  [(size_t)N_*128];
__device__ __align__(16) float g_AB  [(size_t)N_*256];   // Asrc | Bdst

// packed weights: [n][kpad/2] uint32 (bf16x2 pairs along k)
__device__ __align__(16) uint32_t wp_W1h[512*136], wp_W1l[512*136];   // g1wl|g1wr, kpad=272
__device__ __align__(16) uint32_t wp_Weh[512*32],  wp_Wel[512*32];    // g1we|g2we|c1w_e, kpad=64
__device__ __align__(16) uint32_t wp_W2h[256*64],  wp_W2l[256*64];    // g2wl|g2wr, kpad=128
__device__ __align__(16) uint32_t wp_ABh[256*64],  wp_ABl[256*64];    // c1w_a|c1w_b, kpad=128
__device__ __align__(16) uint32_t wp_Ebh[128*32],  wp_Ebl[128*32];    // epw, kpad=64
__device__ __align__(16) uint32_t wp_C2h[64*64],   wp_C2l[64*64];     // c2w, kpad=128

// ---------------------------------------------------------------------------
// Helpers
// ---------------------------------------------------------------------------
__device__ __forceinline__ void red4(float* addr, float4 v) {
    asm volatile("red.global.add.v4.f32 [%0], {%1,%2,%3,%4};"
                 :: "l"(addr), "f"(v.x), "f"(v.y), "f"(v.z), "f"(v.w) : "memory");
}
__device__ __forceinline__ void red2(float* addr, float a, float b) {
    asm volatile("red.global.add.v2.f32 [%0], {%1,%2};"
                 :: "l"(addr), "f"(a), "f"(b) : "memory");
}

__device__ __forceinline__ void mma_bf16(float* c, const uint32_t* a, const uint32_t* b) {
    asm volatile(
        "mma.sync.aligned.m16n8k16.row.col.f32.bf16.bf16.f32 "
        "{%0,%1,%2,%3}, {%4,%5,%6,%7}, {%8,%9}, {%0,%1,%2,%3};"
        : "+f"(c[0]), "+f"(c[1]), "+f"(c[2]), "+f"(c[3])
        : "r"(a[0]), "r"(a[1]), "r"(a[2]), "r"(a[3]), "r"(b[0]), "r"(b[1]));
}

__device__ __forceinline__ uint32_t pack_bf(__nv_bfloat16 a, __nv_bfloat16 b) {
    __nv_bfloat162 t; t.x = a; t.y = b;
    uint32_t r; memcpy(&r, &t, 4); return r;
}

__device__ __forceinline__ void split2(float x, float y, uint32_t& hi, uint32_t& lo) {
    __nv_bfloat16 hx = __float2bfloat16_rn(x);
    __nv_bfloat16 hy = __float2bfloat16_rn(y);
    __nv_bfloat16 lx = __float2bfloat16_rn(x - __bfloat162float(hx));
    __nv_bfloat16 ly = __float2bfloat16_rn(y - __bfloat162float(hy));
    hi = pack_bf(hx, hy);
    lo = pack_bf(lx, ly);
}

// smem layout: s[row][k2] with k2 XOR-swizzled by (row&7); stride 8 uint32.
__device__ __forceinline__ uint32_t lds_sw(const uint32_t* s, int r, int k2) {
    return s[r * 8 + (k2 ^ (r & 7))];
}
__device__ __forceinline__ void sts_pair(uint32_t* s, int m, int k2, uint32_t u0, uint32_t u1) {
    int x = m & 7;
    int p0 = k2 ^ x;
    if (x & 1) { uint32_t t = u0; u0 = u1; u1 = t; }
    *(uint2*)&s[m * 8 + (p0 & ~1)] = make_uint2(u0, u1);
}

// ---------------------------------------------------------------------------
// Tensor-core GEMM, bf16x3 compensated, packed weights, pipelined.
// EPI: 0 = fp32 store; 2 = +bias, relu, red.v2 scatter to g_xout/g_xin.
// ---------------------------------------------------------------------------
template<int EPI>
__global__ __launch_bounds__(256, 2)
void gemm_pk(const float* __restrict__ A,
             const uint32_t* __restrict__ Wh, const uint32_t* __restrict__ Wl,
             const float* __restrict__ bias, float* __restrict__ C,
             int M, int N, int K, int lda, int ldc,
             const int* __restrict__ src, const int* __restrict__ dst)
{
    constexpr int BM = 128, BN = 128;
    __shared__ __align__(16) uint32_t sAh[BM*8], sAl[BM*8], sBh[BN*8], sBl[BN*8];

    const int bm = blockIdx.y * BM, bn = blockIdx.x * BN;
    const int tid = threadIdx.x, wid = tid >> 5, lane = tid & 31;
    const int wm = (wid & 3) * 32, wn = (wid >> 2) * 64;
    const int g = lane >> 2, tig = lane & 3;
    const int wstride = K >> 1;

    const int am0 = tid >> 2, af = tid & 3;
    const int am1 = 64 + (tid >> 2);
    const int wns = tid >> 1, wpart = tid & 1;

    float acc[2][8][4] = {};
    float4 pa0, pa1; uint4 pwh, pwl;

    {   // prologue: tile 0
        int gm0 = bm + am0, gm1 = bm + am1;
        pa0 = (gm0 < M) ? *(const float4*)&A[(size_t)gm0 * lda + af * 4] : make_float4(0,0,0,0);
        pa1 = (gm1 < M) ? *(const float4*)&A[(size_t)gm1 * lda + af * 4] : make_float4(0,0,0,0);
        size_t off = (size_t)(bn + wns) * wstride + wpart * 4;
        pwh = *(const uint4*)&Wh[off];
        pwl = *(const uint4*)&Wl[off];
    }

    const int KT = K >> 4;
    for (int kt = 0; kt < KT; kt++) {
        {
            uint32_t h0, l0, h1, l1;
            split2(pa0.x, pa0.y, h0, l0);
            split2(pa0.z, pa0.w, h1, l1);
            sts_pair(sAh, am0, af * 2, h0, h1);
            sts_pair(sAl, am0, af * 2, l0, l1);
            split2(pa1.x, pa1.y, h0, l0);
            split2(pa1.z, pa1.w, h1, l1);
            sts_pair(sAh, am1, af * 2, h0, h1);
            sts_pair(sAl, am1, af * 2, l0, l1);
            sts_pair(sBh, wns, wpart * 4 + 0, pwh.x, pwh.y);
            sts_pair(sBh, wns, wpart * 4 + 2, pwh.z, pwh.w);
            sts_pair(sBl, wns, wpart * 4 + 0, pwl.x, pwl.y);
            sts_pair(sBl, wns, wpart * 4 + 2, pwl.z, pwl.w);
        }
        __syncthreads();

        if (kt + 1 < KT) {
            int k0 = (kt + 1) * 16;
            int gm0 = bm + am0, gm1 = bm + am1;
            pa0 = (gm0 < M) ? *(const float4*)&A[(size_t)gm0 * lda + k0 + af * 4] : make_float4(0,0,0,0);
            pa1 = (gm1 < M) ? *(const float4*)&A[(size_t)gm1 * lda + k0 + af * 4] : make_float4(0,0,0,0);
            size_t off = (size_t)(bn + wns) * wstride + (k0 >> 1) + wpart * 4;
            pwh = *(const uint4*)&Wh[off];
            pwl = *(const uint4*)&Wl[off];
        }

        uint32_t ah[2][4], al[2][4];
        #pragma unroll
        for (int mt = 0; mt < 2; mt++) {
            int r0 = wm + mt * 16 + g;
            ah[mt][0] = lds_sw(sAh, r0,     tig);
            ah[mt][1] = lds_sw(sAh, r0 + 8, tig);
            ah[mt][2] = lds_sw(sAh, r0,     tig + 4);
            ah[mt][3] = lds_sw(sAh, r0 + 8, tig + 4);
            al[mt][0] = lds_sw(sAl, r0,     tig);
            al[mt][1] = lds_sw(sAl, r0 + 8, tig);
            al[mt][2] = lds_sw(sAl, r0,     tig + 4);
            al[mt][3] = lds_sw(sAl, r0 + 8, tig + 4);
        }
        #pragma unroll
        for (int nt = 0; nt < 8; nt++) {
            int n = wn + nt * 8 + g;
            uint32_t bh[2], bl[2];
            bh[0] = lds_sw(sBh, n, tig);
            bh[1] = lds_sw(sBh, n, tig + 4);
            bl[0] = lds_sw(sBl, n, tig);
            bl[1] = lds_sw(sBl, n, tig + 4);
            #pragma unroll
            for (int mt = 0; mt < 2; mt++) {
                mma_bf16(acc[mt][nt], ah[mt], bh);
                mma_bf16(acc[mt][nt], al[mt], bh);
                mma_bf16(acc[mt][nt], ah[mt], bl);
            }
        }
        __syncthreads();
    }

    #pragma unroll
    for (int mt = 0; mt < 2; mt++) {
        #pragma unroll
        for (int half = 0; half < 2; half++) {
            int r = bm + wm + mt * 16 + g + half * 8;
            if (r >= M) continue;
            int s = 0, d = 0;
            if (EPI == 2) { s = src[r]; d = dst[r]; }
            #pragma unroll
            for (int nt = 0; nt < 8; nt++) {
                int col0 = bn + wn + nt * 8 + tig * 2;
                float v0 = acc[mt][nt][half * 2 + 0];
                float v1 = acc[mt][nt][half * 2 + 1];
                if (EPI == 2) {
                    v0 = fmaxf(v0 + bias[col0], 0.f);
                    v1 = fmaxf(v1 + bias[col0 + 1], 0.f);
                    red2(&g_xout[(size_t)s * 128 + col0], v0, v1);
                    red2(&g_xin [(size_t)d * 128 + col0], v0, v1);
                } else {
                    *(float2*)&C[(size_t)r * ldc + col0] = make_float2(v0, v1);
                }
            }
        }
    }
}

// ---------------------------------------------------------------------------
// Pack weights into bf16 hi/lo uint32, n-major [n][kpad/2]. One launch.
// ---------------------------------------------------------------------------
__global__ void k_pack(const float* __restrict__ g1wl, const float* __restrict__ g1wr,
                       const float* __restrict__ g1we, const float* __restrict__ g2we,
                       const float* __restrict__ c1w,  const float* __restrict__ g2wl,
                       const float* __restrict__ g2wr, const float* __restrict__ epw,
                       const float* __restrict__ c2w)
{
    const float* W; int K, N, n0, kpad; uint32_t *dh, *dl;
    switch (blockIdx.y) {
        case 0: W = g1wl;           K = 258; N = 256; n0 = 0;   kpad = 272; dh = wp_W1h; dl = wp_W1l; break;
        case 1: W = g1wr;           K = 258; N = 256; n0 = 256; kpad = 272; dh = wp_W1h; dl = wp_W1l; break;
        case 2: W = g1we;           K = 64;  N = 256; n0 = 0;   kpad = 64;  dh = wp_Weh; dl = wp_Wel; break;
        case 3: W = g2we;           K = 64;  N = 128; n0 = 256; kpad = 64;  dh = wp_Weh; dl = wp_Wel; break;
        case 4: W = c1w + 256*128;  K = 64;  N = 128; n0 = 384; kpad = 64;  dh = wp_Weh; dl = wp_Wel; break;
        case 5: W = g2wl;           K = 128; N = 128; n0 = 0;   kpad = 128; dh = wp_W2h; dl = wp_W2l; break;
        case 6: W = g2wr;           K = 128; N = 128; n0 = 128; kpad = 128; dh = wp_W2h; dl = wp_W2l; break;
        case 7: W = c1w;            K = 128; N = 128; n0 = 0;   kpad = 128; dh = wp_ABh; dl = wp_ABl; break;
        case 8: W = c1w + 128*128;  K = 128; N = 128; n0 = 128; kpad = 128; dh = wp_ABh; dl = wp_ABl; break;
        case 9: W = epw;            K = 64;  N = 128; n0 = 0;   kpad = 64;  dh = wp_Ebh; dl = wp_Ebl; break;
        default: W = c2w;           K = 128; N = 64;  n0 = 0;   kpad = 128; dh = wp_C2h; dl = wp_C2l; break;
    }
    int kh = kpad >> 1;
    int total = N * kh;
    for (int i = blockIdx.x * blockDim.x + threadIdx.x; i < total; i += gridDim.x * blockDim.x) {
        int n = i / kh, k2 = i - n * kh, k = k2 * 2;
        float v0 = (k     < K) ? W[(size_t)k * N + n]       : 0.f;
        float v1 = (k + 1 < K) ? W[(size_t)(k + 1) * N + n] : 0.f;
        uint32_t hi, lo; split2(v0, v1, hi, lo);
        dh[(size_t)(n0 + n) * kh + k2] = hi;
        dl[(size_t)(n0 + n) * kh + k2] = lo;
    }
}

// ---------------------------------------------------------------------------
// Degrees + loop_attr sum. 1 warp / edge.
// ---------------------------------------------------------------------------
__global__ void k_deg_loop(const int* __restrict__ src, const int* __restrict__ dst,
                           const float* __restrict__ ea) {
    int warp = (blockIdx.x * 256 + threadIdx.x) >> 5;
    int lane = threadIdx.x & 31;
    if (warp >= E_) return;
    int s = src[warp], d = dst[warp];
    if (lane == 0) atomicAdd(&g_deg_out[s], 1);
    if (lane == 1) atomicAdd(&g_deg_in[d], 1);
    if (lane < 16) {
        float4 a = reinterpret_cast<const float4*>(ea + (size_t)warp * 64)[lane];
        red4(&g_loop[(size_t)d * 64 + lane * 4], a);
    }
}

// ---------------------------------------------------------------------------
// Build xi (stride 272); finalize loop_attr. 1 warp / node, float4 I/O.
// ---------------------------------------------------------------------------
__global__ void k_build_xi(const float* __restrict__ node_stats) {
    int warp = (blockIdx.x * 256 + threadIdx.x) >> 5;
    int lane = threadIdx.x & 31;
    if (warp >= N_) return;
    float io = 1.f / fmaxf((float)g_deg_out[warp], 1.f);
    float ii = 1.f / fmaxf((float)g_deg_in[warp], 1.f);
    float4 o = ((const float4*)(g_xout + (size_t)warp * 128))[lane];
    float4 i4 = ((const float4*)(g_xin  + (size_t)warp * 128))[lane];
    o.x *= io; o.y *= io; o.z *= io; o.w *= io;
    i4.x *= ii; i4.y *= ii; i4.z *= ii; i4.w *= ii;
    float* xi = g_xi + (size_t)warp * 272;
    ((float4*)xi)[lane] = o;
    ((float4*)(xi + 128))[lane] = i4;
    if (lane < 4) {
        float4 p = make_float4(0.f, 0.f, 0.f, 0.f);
        if (lane == 0) { p.x = node_stats[(size_t)warp * 2]; p.y = node_stats[(size_t)warp * 2 + 1]; }
        ((float4*)(xi + 256))[lane] = p;
    }
    if (lane < 16) {
        float4 l4 = ((float4*)(g_loop + (size_t)warp * 64))[lane];
        l4.x *= ii; l4.y *= ii; l4.z *= ii; l4.w *= ii;
        ((float4*)(g_loop + (size_t)warp * 64))[lane] = l4;
    }
}

// ---------------------------------------------------------------------------
// Fused GATv2 attention over REAL edges only (self-loops live in k_node).
// 1 warp / edge, grid = E/8 exactly, no bounds checks.
// ---------------------------------------------------------------------------
template<int H>
__global__ void k_attn(const float* __restrict__ x, int xstr, int xroff,
                       const float* __restrict__ ewE, int ewstr,
                       const float* __restrict__ att,
                       const int* __restrict__ src, const int* __restrict__ dst,
                       float* __restrict__ den, float* __restrict__ osum)
{
    const int CH = H * 128;
    __shared__ float satt[CH];
    if (threadIdx.x < CH) satt[threadIdx.x] = att[threadIdx.x];
    __syncthreads();
    int warp = (blockIdx.x * 256 + threadIdx.x) >> 5;
    int lane = threadIdx.x & 31;
    int s = src[warp], d = dst[warp];
    const float* ew = ewE + (size_t)warp * ewstr;
    const float* pl = x + (size_t)s * xstr;
    const float* pr = x + (size_t)d * xstr + xroff;

    float4 xlv[H];
    float lg[H];
    #pragma unroll
    for (int h = 0; h < H; h++) {
        int off = h * 128 + lane * 4;
        float4 l4 = *(const float4*)&pl[off];
        float4 r4 = *(const float4*)&pr[off];
        float4 e4 = *(const float4*)&ew[off];
        float4 a4 = *(const float4*)&satt[off];
        xlv[h] = l4;
        float v0 = l4.x + r4.x + e4.x; v0 = (v0 > 0.f) ? v0 : 0.2f * v0;
        float v1 = l4.y + r4.y + e4.y; v1 = (v1 > 0.f) ? v1 : 0.2f * v1;
        float v2 = l4.z + r4.z + e4.z; v2 = (v2 > 0.f) ? v2 : 0.2f * v2;
        float v3 = l4.w + r4.w + e4.w; v3 = (v3 > 0.f) ? v3 : 0.2f * v3;
        lg[h] = v0 * a4.x + v1 * a4.y + v2 * a4.z + v3 * a4.w;
    }
    #pragma unroll
    for (int h = 0; h < H; h++)
        #pragma unroll
        for (int o = 16; o > 0; o >>= 1)
            lg[h] += __shfl_xor_sync(0xffffffffu, lg[h], o);
    float a[H];
    #pragma unroll
    for (int h = 0; h < H; h++) a[h] = expf(lg[h]);
    if (lane == 0) {
        #pragma unroll
        for (int h = 0; h < H; h++) atomicAdd(&den[(size_t)d * H + h], a[h]);
    }
    #pragma unroll
    for (int h = 0; h < H; h++) {
        float4 v = xlv[h];
        v.x *= a[h]; v.y *= a[h]; v.z *= a[h]; v.w *= a[h];
        red4(&osum[((size_t)d * H + h) * 128 + lane * 4], v);
    }
}

// ---------------------------------------------------------------------------
// Node finalize WITH self-loop absorption:
//   a_loop = exp(logit(xl[n], xr[n], ewL[n]))
//   den_tot = den + a_loop;  osum_tot = osum + a_loop * xl[n]
// then head mean + bias, layernorm, elu. 1 warp / node, 256-thread blocks.
// ---------------------------------------------------------------------------
template<int H>
__global__ void k_node(const float* __restrict__ osum, const float* __restrict__ den,
                       const float* __restrict__ x, int xstr, int xroff,
                       const float* __restrict__ ewL, int ewLstr,
                       const float* __restrict__ att,
                       const float* __restrict__ bias,
                       const float* __restrict__ lng, const float* __restrict__ lnb,
                       float* __restrict__ out)
{
    const int CH = H * 128;
    __shared__ float satt[CH];
    if (threadIdx.x < CH) satt[threadIdx.x] = att[threadIdx.x];
    __syncthreads();
    int warp = (blockIdx.x * 256 + threadIdx.x) >> 5;
    int lane = threadIdx.x & 31;
    if (warp >= N_) return;
    int n = warp;

    // ---- self-loop logit + xl values ----
    const float* pl = x + (size_t)n * xstr;
    const float* pr = pl + xroff;
    const float* ew = ewL + (size_t)n * ewLstr;
    float xlv[H][4];
    float lg[H];
    #pragma unroll
    for (int h = 0; h < H; h++) {
        lg[h] = 0.f;
        #pragma unroll
        for (int i = 0; i < 4; i++) {
            int c = h * 128 + i * 32 + lane;
            float l = pl[c];
            float v = l + pr[c] + ew[c];
            v = (v > 0.f) ? v : 0.2f * v;
            xlv[h][i] = l;
            lg[h] += v * satt[c];
        }
    }
    #pragma unroll
    for (int h = 0; h < H; h++)
        #pragma unroll
        for (int o = 16; o > 0; o >>= 1)
            lg[h] += __shfl_xor_sync(0xffffffffu, lg[h], o);
    float aL[H], dinv[H];
    #pragma unroll
    for (int h = 0; h < H; h++) {
        aL[h] = expf(lg[h]);
        dinv[h] = 1.f / fmaxf(den[(size_t)n * H + h] + aL[h], 1e-16f);
    }

    // ---- combine heads, layernorm, elu ----
    float v[4];
    float sum = 0.f;
    #pragma unroll
    for (int i = 0; i < 4; i++) {
        int c = i * 32 + lane;
        float o = 0.f;
        #pragma unroll
        for (int h = 0; h < H; h++)
            o += (osum[((size_t)n * H + h) * 128 + c] + aL[h] * xlv[h][i]) * dinv[h];
        o = o * (1.f / H) + bias[c];
        v[i] = o;
        sum += o;
    }
    #pragma unroll
    for (int o = 16; o > 0; o >>= 1) sum += __shfl_xor_sync(0xffffffffu, sum, o);
    float mu = sum * (1.f / 128.f);
    float var = 0.f;
    #pragma unroll
    for (int i = 0; i < 4; i++) { float t = v[i] - mu; var += t * t; }
    #pragma unroll
    for (int o = 16; o > 0; o >>= 1) var += __shfl_xor_sync(0xffffffffu, var, o);
    var *= (1.f / 128.f);
    float rs = rsqrtf(var + 1e-5f);
    #pragma unroll
    for (int i = 0; i < 4; i++) {
        int c = i * 32 + lane;
        float hn = (v[i] - mu) * rs * lng[c] + lnb[c];
        hn = (hn > 0.f) ? hn : expm1f(hn);
        out[(size_t)n * 128 + c] = hn;
    }
}

// ---------------------------------------------------------------------------
// Fully fused classifier (two MMA stages, no Cea materialization).
// ---------------------------------------------------------------------------
__global__ __launch_bounds__(256, 2)
void k_classifier(const int* __restrict__ src, const int* __restrict__ dst,
                  const float* __restrict__ ea,
                  const uint32_t* __restrict__ W1h, const uint32_t* __restrict__ W1l,
                  const uint32_t* __restrict__ W2h, const uint32_t* __restrict__ W2l,
                  const float* __restrict__ c1b, const float* __restrict__ c2b,
                  const float* __restrict__ c3w, const float* __restrict__ c3b,
                  float* __restrict__ out)
{
    extern __shared__ __align__(16) char smem_raw[];
    uint32_t* sAh = (uint32_t*)smem_raw;        // 128*8
    uint32_t* sAl = sAh + 128*8;                // 128*8
    uint32_t* s2h = sAl + 128*8;                // 128*64
    uint32_t* s2l = s2h + 128*64;               // 128*64
    int*   ssrc   = (int*)(s2l + 128*64);       // 128
    int*   sdst   = ssrc + 128;                 // 128
    float* rowsum = (float*)(sdst + 128);       // 128

    const int bm = blockIdx.x * 128;
    const int tid = threadIdx.x, wid = tid >> 5, lane = tid & 31;
    const int wm = (wid & 3) * 32;
    const int wn = (wid >> 2) * 64;
    const int wn2 = (wid >> 2) * 32;
    const int g = lane >> 2, tig = lane & 3;
    const int am0 = tid >> 2, af = tid & 3;
    const int am1 = 64 + (tid >> 2);

    if (tid < 128) {
        ssrc[tid] = src[bm + tid];
        sdst[tid] = dst[bm + tid];
        rowsum[tid] = 0.f;
    }

    // stage 1: T = ea @ c1w_e
    float acc1[2][8][4] = {};
    for (int kt = 0; kt < 4; kt++) {
        int k0 = kt * 16;
        {
            float4 a0 = *(const float4*)&ea[(size_t)(bm + am0) * 64 + k0 + af * 4];
            float4 a1 = *(const float4*)&ea[(size_t)(bm + am1) * 64 + k0 + af * 4];
            uint32_t h0, l0, h1, l1;
            split2(a0.x, a0.y, h0, l0); split2(a0.z, a0.w, h1, l1);
            sts_pair(sAh, am0, af * 2, h0, h1); sts_pair(sAl, am0, af * 2, l0, l1);
            split2(a1.x, a1.y, h0, l0); split2(a1.z, a1.w, h1, l1);
            sts_pair(sAh, am1, af * 2, h0, h1); sts_pair(sAl, am1, af * 2, l0, l1);
        }
        __syncthreads();

        uint32_t ah[2][4], al[2][4];
        #pragma unroll
        for (int mt = 0; mt < 2; mt++) {
            int r0 = wm + mt * 16 + g;
            ah[mt][0] = lds_sw(sAh, r0,     tig);
            ah[mt][1] = lds_sw(sAh, r0 + 8, tig);
            ah[mt][2] = lds_sw(sAh, r0,     tig + 4);
            ah[mt][3] = lds_sw(sAh, r0 + 8, tig + 4);
            al[mt][0] = lds_sw(sAl, r0,     tig);
            al[mt][1] = lds_sw(sAl, r0 + 8, tig);
            al[mt][2] = lds_sw(sAl, r0,     tig + 4);
            al[mt][3] = lds_sw(sAl, r0 + 8, tig + 4);
        }
        #pragma unroll
        for (int nt = 0; nt < 8; nt++) {
            int n = wn + nt * 8 + g;
            uint32_t bh[2], bl[2];
            bh[0] = __ldg(&W1h[n * 32 + kt * 8 + tig]);
            bh[1] = __ldg(&W1h[n * 32 + kt * 8 + tig + 4]);
            bl[0] = __ldg(&W1l[n * 32 + kt * 8 + tig]);
            bl[1] = __ldg(&W1l[n * 32 + kt * 8 + tig + 4]);
            #pragma unroll
            for (int mt = 0; mt < 2; mt++) {
                mma_bf16(acc1[mt][nt], ah[mt], bh);
                mma_bf16(acc1[mt][nt], al[mt], bh);
                mma_bf16(acc1[mt][nt], ah[mt], bl);
            }
        }
        __syncthreads();
    }

    // epilogue 1
    #pragma unroll
    for (int mt = 0; mt < 2; mt++) {
        #pragma unroll
        for (int half = 0; half < 2; half++) {
            int r = wm + mt * 16 + g + half * 8;
            int s = ssrc[r], d = sdst[r];
            #pragma unroll
            for (int nt = 0; nt < 8; nt++) {
                int col0 = wn + nt * 8 + tig * 2;
                float v0 = acc1[mt][nt][half * 2 + 0]
                         + g_AB[(size_t)s * 256 + col0]
                         + g_AB[(size_t)d * 256 + 128 + col0] + c1b[col0];
                float v1 = acc1[mt][nt][half * 2 + 1]
                         + g_AB[(size_t)s * 256 + col0 + 1]
                         + g_AB[(size_t)d * 256 + 128 + col0 + 1] + c1b[col0 + 1];
                v0 = fmaxf(v0, 0.f); v1 = fmaxf(v1, 0.f);
                uint32_t hi, lo; split2(v0, v1, hi, lo);
                int k2 = col0 >> 1;
                int sw = k2 ^ ((r & 7) << 3);
                s2h[r * 64 + sw] = hi;
                s2l[r * 64 + sw] = lo;
            }
        }
    }
    __syncthreads();

    // stage 2: T @ c2w
    float acc2[2][4][4] = {};
    #pragma unroll
    for (int kt2 = 0; kt2 < 8; kt2++) {
        uint32_t ah[2][4], al[2][4];
        #pragma unroll
        for (int mt = 0; mt < 2; mt++) {
            int r0 = wm + mt * 16 + g;
            int r1 = r0 + 8;
            int x0 = (r0 & 7) << 3, x1 = (r1 & 7) << 3;
            ah[mt][0] = s2h[r0 * 64 + ((kt2 * 8 + tig)     ^ x0)];
            ah[mt][1] = s2h[r1 * 64 + ((kt2 * 8 + tig)     ^ x1)];
            ah[mt][2] = s2h[r0 * 64 + ((kt2 * 8 + tig + 4) ^ x0)];
            ah[mt][3] = s2h[r1 * 64 + ((kt2 * 8 + tig + 4) ^ x1)];
            al[mt][0] = s2l[r0 * 64 + ((kt2 * 8 + tig)     ^ x0)];
            al[mt][1] = s2l[r1 * 64 + ((kt2 * 8 + tig)     ^ x1)];
            al[mt][2] = s2l[r0 * 64 + ((kt2 * 8 + tig + 4) ^ x0)];
            al[mt][3] = s2l[r1 * 64 + ((kt2 * 8 + tig + 4) ^ x1)];
        }
        #pragma unroll
        for (int nt = 0; nt < 4; nt++) {
            int n = wn2 + nt * 8 + g;
            uint32_t bh[2], bl[2];
            bh[0] = __ldg(&W2h[n * 64 + kt2 * 8 + tig]);
            bh[1] = __ldg(&W2h[n * 64 + kt2 * 8 + tig + 4]);
            bl[0] = __ldg(&W2l[n * 64 + kt2 * 8 + tig]);
            bl[1] = __ldg(&W2l[n * 64 + kt2 * 8 + tig + 4]);
            #pragma unroll
            for (int mt = 0; mt < 2; mt++) {
                mma_bf16(acc2[mt][nt], ah[mt], bh);
                mma_bf16(acc2[mt][nt], al[mt], bh);
                mma_bf16(acc2[mt][nt], ah[mt], bl);
            }
        }
    }

    // epilogue 2
    #pragma unroll
    for (int mt = 0; mt < 2; mt++) {
        #pragma unroll
        for (int half = 0; half < 2; half++) {
            int r = wm + mt * 16 + g + half * 8;
            float p = 0.f;
            #pragma unroll
            for (int nt = 0; nt < 4; nt++) {
                int col = wn2 + nt * 8 + tig * 2;
                float t0 = fmaxf(acc2[mt][nt][half * 2 + 0] + c2b[col], 0.f);
                float t1 = fmaxf(acc2[mt][nt][half * 2 + 1] + c2b[col + 1], 0.f);
                p += t0 * c3w[col] + t1 * c3w[col + 1];
            }
            atomicAdd(&rowsum[r], p);
        }
    }
    __syncthreads();
    if (tid < 128) out[bm + tid] = rowsum[tid] + c3b[0];
}

// ---------------------------------------------------------------------------
// Host launch
// ---------------------------------------------------------------------------
static void* sym(const void* s) { void* p = nullptr; cudaGetSymbolAddress(&p, s); return p; }

static inline dim3 ggrid(int M, int N) { return dim3((N + 127) / 128, (M + 127) / 128); }

#define SMEM_CLS ((128*8*2 + 128*64*2) * 4 + 128*4*2 + 128*4)

extern "C" void kernel_launch(void* const* d_in, const int* in_sizes, int n_in,
                              void* d_out, int out_size)
{
    const float* node_stats = (const float*)d_in[1];
    const int*   edge_index = (const int*)  d_in[2];
    const float* edge_attr  = (const float*)d_in[3];
    const float* epw  = (const float*)d_in[4];
    const float* epb  = (const float*)d_in[5];
    const float* g1wl = (const float*)d_in[6];
    const float* g1wr = (const float*)d_in[7];
    const float* g1we = (const float*)d_in[8];
    const float* g1att= (const float*)d_in[9];
    const float* g1b  = (const float*)d_in[10];
    const float* n1g  = (const float*)d_in[11];
    const float* n1b  = (const float*)d_in[12];
    const float* g2wl = (const float*)d_in[13];
    const float* g2wr = (const float*)d_in[14];
    const float* g2we = (const float*)d_in[15];
    const float* g2att= (const float*)d_in[16];
    const float* g2b  = (const float*)d_in[17];
    const float* n2g  = (const float*)d_in[18];
    const float* n2b  = (const float*)d_in[19];
    const float* c1w  = (const float*)d_in[20];
    const float* c1b  = (const float*)d_in[21];
    const float* c2w  = (const float*)d_in[22];
    const float* c2b  = (const float*)d_in[23];
    const float* c3w  = (const float*)d_in[24];
    const float* c3b  = (const float*)d_in[25];

    const int* src = edge_index;
    const int* dst = edge_index + E_;
    float* out = (float*)d_out;

    float* p_xi   = (float*)sym(g_xi);
    float* p_loop = (float*)sym(g_loop);
    float* p_x1   = (float*)sym(g_x1);
    float* p_ew   = (float*)sym(g_ew);
    float* p_ewL  = (float*)sym(g_ewL);
    float* p_den1 = (float*)sym(g_den1);
    float* p_os1  = (float*)sym(g_osum1);
    float* p_h1   = (float*)sym(g_h1);
    float* p_x2   = (float*)sym(g_x2);
    float* p_den2 = (float*)sym(g_den2);
    float* p_os2  = (float*)sym(g_osum2);
    float* p_h2   = (float*)sym(g_h2);
    float* p_AB   = (float*)sym(g_AB);

    const uint32_t* p_W1h = (const uint32_t*)sym(wp_W1h);
    const uint32_t* p_W1l = (const uint32_t*)sym(wp_W1l);
    const uint32_t* p_Weh = (const uint32_t*)sym(wp_Weh);
    const uint32_t* p_Wel = (const uint32_t*)sym(wp_Wel);
    const uint32_t* p_W2h = (const uint32_t*)sym(wp_W2h);
    const uint32_t* p_W2l = (const uint32_t*)sym(wp_W2l);
    const uint32_t* p_ABh = (const uint32_t*)sym(wp_ABh);
    const uint32_t* p_ABl = (const uint32_t*)sym(wp_ABl);
    const uint32_t* p_Ebh = (const uint32_t*)sym(wp_Ebh);
    const uint32_t* p_Ebl = (const uint32_t*)sym(wp_Ebl);
    const uint32_t* p_C2h = (const uint32_t*)sym(wp_C2h);
    const uint32_t* p_C2l = (const uint32_t*)sym(wp_C2l);

    static bool attr_set = false;
    if (!attr_set) {
        cudaFuncSetAttribute(k_classifier, cudaFuncAttributeMaxDynamicSharedMemorySize, SMEM_CLS);
        attr_set = true;
    }

    // ---- zero accumulators ----
    cudaMemsetAsync(sym(g_deg_out), 0, (size_t)N_ * 4);
    cudaMemsetAsync(sym(g_deg_in),  0, (size_t)N_ * 4);
    cudaMemsetAsync(sym(g_xout),    0, (size_t)N_ * 128 * 4);
    cudaMemsetAsync(sym(g_xin),     0, (size_t)N_ * 128 * 4);
    cudaMemsetAsync(p_loop,         0, (size_t)N_ * 64 * 4);
    cudaMemsetAsync(p_den1,         0, (size_t)N_ * 2 * 4);
    cudaMemsetAsync(p_os1,          0, (size_t)N_ * 256 * 4);
    cudaMemsetAsync(p_den2,         0, (size_t)N_ * 4);
    cudaMemsetAsync(p_os2,          0, (size_t)N_ * 128 * 4);

    // ---- weight packing ----
    k_pack<<<dim3(144, 11), 256>>>(g1wl, g1wr, g1we, g2we, c1w, g2wl, g2wr, epw, c2w);

    // ---- phase 1: degrees, loop sums, emb GEMM fused with scatter ----
    k_deg_loop<<<(E_ + 7) / 8, 256>>>(src, dst, edge_attr);
    gemm_pk<2><<<ggrid(E_, 128), 256>>>(edge_attr, p_Ebh, p_Ebl, epb, nullptr,
                                        E_, 128, 64, 64, 0, src, dst);
    k_build_xi<<<(N_ + 7) / 8, 256>>>(node_stats);

    // ---- combined GEMMs ----
    gemm_pk<0><<<ggrid(N_, 512), 256>>>(p_xi, p_W1h, p_W1l, nullptr, p_x1,
                                        N_, 512, 272, 272, 512, nullptr, nullptr);
    gemm_pk<0><<<ggrid(E_, 384), 256>>>(edge_attr, p_Weh, p_Wel, nullptr, p_ew,
                                        E_, 384, 64, 64, 384, nullptr, nullptr);
    gemm_pk<0><<<ggrid(N_, 384), 256>>>(p_loop, p_Weh, p_Wel, nullptr, p_ewL,
                                        N_, 384, 64, 64, 384, nullptr, nullptr);

    // ---- GAT layer 1 (heads=2) ----
    k_attn<2><<<E_ / 8, 256>>>(p_x1, 512, 256, p_ew, 384, g1att, src, dst, p_den1, p_os1);
    k_node<2><<<(N_ + 7) / 8, 256>>>(p_os1, p_den1, p_x1, 512, 256, p_ewL, 384,
                                     g1att, g1b, n1g, n1b, p_h1);

    // ---- GAT layer 2 (heads=1) ----
    gemm_pk<0><<<ggrid(N_, 256), 256>>>(p_h1, p_W2h, p_W2l, nullptr, p_x2,
                                        N_, 256, 128, 128, 256, nullptr, nullptr);
    k_attn<1><<<E_ / 8, 256>>>(p_x2, 256, 128, p_ew + 256, 384, g2att, src, dst, p_den2, p_os2);
    k_node<1><<<(N_ + 7) / 8, 256>>>(p_os2, p_den2, p_x2, 256, 128, p_ewL + 256, 384,
                                     g2att, g2b, n2g, n2b, p_h2);

    // ---- classifier ----
    gemm_pk<0><<<ggrid(N_, 256), 256>>>(p_h2, p_ABh, p_ABl, nullptr, p_AB,
                                        N_, 256, 128, 128, 256, nullptr, nullptr);
    k_classifier<<<E_ / 128, 256, SMEM_CLS>>>(src, dst, edge_attr,
                                              p_Weh + 384 * 32, p_Wel + 384 * 32,
                                              p_C2h, p_C2l,
                                              c1b, c2b, c3w, c3b, out);
}

// round 11
// speedup vs baseline: 1.2648x; 1.0424x over previous
#include <cuda_runtime.h>
#include <cuda_bf16.h>
#include <cuda_fp16.h>
#include <math.h>
#include <stdint.h>

// ---------------------------------------------------------------------------
// Problem constants
// ---------------------------------------------------------------------------
#define N_   50000
#define E_   400000
// ND=128, ED=64, HID=128, GIN=258 (padded to 272), CIN=320

// ---------------------------------------------------------------------------
// Static device scratch
// ---------------------------------------------------------------------------
__device__ __align__(16) int   g_deg_out[N_];
__device__ __align__(16) int   g_deg_in[N_];
__device__ __align__(16) float g_xout[(size_t)N_*128];
__device__ __align__(16) float g_xin [(size_t)N_*128];
__device__ __align__(16) float g_loop[(size_t)N_*64];
__device__ __align__(16) float g_xi  [(size_t)N_*272];   // zero-padded 258..271
__device__ __align__(16) float g_x1  [(size_t)N_*512];   // xl1 | xr1
__device__ __align__(16) __half g_ewh[(size_t)E_*384];   // ewE1(256) | ewE2(128), fp16 STREAM
__device__ __align__(16) float g_ewL [(size_t)N_*384];   // ewL1(256) | ewL2(128), fp32
__device__ __align__(16) float g_den1[N_*2];
__device__ __align__(16) float g_osum1[(size_t)N_*256];
__device__ __align__(16) float g_h1  [(size_t)N_*128];
__device__ __align__(16) float g_x2  [(size_t)N_*256];   // xl2 | xr2
__device__ __align__(16) float g_den2[N_];
__device__ __align__(16) float g_osum2[(size_t)N_*128];
__device__ __align__(16) float g_h2  [(size_t)N_*128];
__device__ __align__(16) float g_AB  [(size_t)N_*256];   // Asrc | Bdst

// packed weights: [n][kpad/2] uint32 (bf16x2 pairs along k)
__device__ __align__(16) uint32_t wp_W1h[512*136], wp_W1l[512*136];   // g1wl|g1wr, kpad=272
__device__ __align__(16) uint32_t wp_Weh[512*32],  wp_Wel[512*32];    // g1we|g2we|c1w_e, kpad=64
__device__ __align__(16) uint32_t wp_W2h[256*64],  wp_W2l[256*64];    // g2wl|g2wr, kpad=128
__device__ __align__(16) uint32_t wp_ABh[256*64],  wp_ABl[256*64];    // c1w_a|c1w_b, kpad=128
__device__ __align__(16) uint32_t wp_Ebh[128*32],  wp_Ebl[128*32];    // epw, kpad=64
__device__ __align__(16) uint32_t wp_C2h[64*64],   wp_C2l[64*64];     // c2w, kpad=128

// ---------------------------------------------------------------------------
// Helpers
// ---------------------------------------------------------------------------
__device__ __forceinline__ void red4(float* addr, float4 v) {
    asm volatile("red.global.add.v4.f32 [%0], {%1,%2,%3,%4};"
                 :: "l"(addr), "f"(v.x), "f"(v.y), "f"(v.z), "f"(v.w) : "memory");
}
__device__ __forceinline__ void red2(float* addr, float a, float b) {
    asm volatile("red.global.add.v2.f32 [%0], {%1,%2};"
                 :: "l"(addr), "f"(a), "f"(b) : "memory");
}

__device__ __forceinline__ void mma_bf16(float* c, const uint32_t* a, const uint32_t* b) {
    asm volatile(
        "mma.sync.aligned.m16n8k16.row.col.f32.bf16.bf16.f32 "
        "{%0,%1,%2,%3}, {%4,%5,%6,%7}, {%8,%9}, {%0,%1,%2,%3};"
        : "+f"(c[0]), "+f"(c[1]), "+f"(c[2]), "+f"(c[3])
        : "r"(a[0]), "r"(a[1]), "r"(a[2]), "r"(a[3]), "r"(b[0]), "r"(b[1]));
}

__device__ __forceinline__ uint32_t pack_bf(__nv_bfloat16 a, __nv_bfloat16 b) {
    __nv_bfloat162 t; t.x = a; t.y = b;
    uint32_t r; memcpy(&r, &t, 4); return r;
}

__device__ __forceinline__ void split2(float x, float y, uint32_t& hi, uint32_t& lo) {
    __nv_bfloat16 hx = __float2bfloat16_rn(x);
    __nv_bfloat16 hy = __float2bfloat16_rn(y);
    __nv_bfloat16 lx = __float2bfloat16_rn(x - __bfloat162float(hx));
    __nv_bfloat16 ly = __float2bfloat16_rn(y - __bfloat162float(hy));
    hi = pack_bf(hx, hy);
    lo = pack_bf(lx, ly);
}

// smem layout: s[row][k2] with k2 XOR-swizzled by (row&7); stride 8 uint32.
__device__ __forceinline__ uint32_t lds_sw(const uint32_t* s, int r, int k2) {
    return s[r * 8 + (k2 ^ (r & 7))];
}
__device__ __forceinline__ void sts_pair(uint32_t* s, int m, int k2, uint32_t u0, uint32_t u1) {
    int x = m & 7;
    int p0 = k2 ^ x;
    if (x & 1) { uint32_t t = u0; u0 = u1; u1 = t; }
    *(uint2*)&s[m * 8 + (p0 & ~1)] = make_uint2(u0, u1);
}

// ---------------------------------------------------------------------------
// Tensor-core GEMM, bf16x3 compensated, packed weights, pipelined.
// EPI: 0 = fp32 store; 1 = fp16 store; 2 = +bias, relu, red.v2 scatter.
// ---------------------------------------------------------------------------
template<int EPI>
__global__ __launch_bounds__(256, 2)
void gemm_pk(const float* __restrict__ A,
             const uint32_t* __restrict__ Wh, const uint32_t* __restrict__ Wl,
             const float* __restrict__ bias, void* __restrict__ Cv,
             int M, int N, int K, int lda, int ldc,
             const int* __restrict__ src, const int* __restrict__ dst)
{
    constexpr int BM = 128, BN = 128;
    __shared__ __align__(16) uint32_t sAh[BM*8], sAl[BM*8], sBh[BN*8], sBl[BN*8];

    const int bm = blockIdx.y * BM, bn = blockIdx.x * BN;
    const int tid = threadIdx.x, wid = tid >> 5, lane = tid & 31;
    const int wm = (wid & 3) * 32, wn = (wid >> 2) * 64;
    const int g = lane >> 2, tig = lane & 3;
    const int wstride = K >> 1;

    const int am0 = tid >> 2, af = tid & 3;
    const int am1 = 64 + (tid >> 2);
    const int wns = tid >> 1, wpart = tid & 1;

    float acc[2][8][4] = {};
    float4 pa0, pa1; uint4 pwh, pwl;

    {   // prologue: tile 0
        int gm0 = bm + am0, gm1 = bm + am1;
        pa0 = (gm0 < M) ? *(const float4*)&A[(size_t)gm0 * lda + af * 4] : make_float4(0,0,0,0);
        pa1 = (gm1 < M) ? *(const float4*)&A[(size_t)gm1 * lda + af * 4] : make_float4(0,0,0,0);
        size_t off = (size_t)(bn + wns) * wstride + wpart * 4;
        pwh = *(const uint4*)&Wh[off];
        pwl = *(const uint4*)&Wl[off];
    }

    const int KT = K >> 4;
    for (int kt = 0; kt < KT; kt++) {
        {
            uint32_t h0, l0, h1, l1;
            split2(pa0.x, pa0.y, h0, l0);
            split2(pa0.z, pa0.w, h1, l1);
            sts_pair(sAh, am0, af * 2, h0, h1);
            sts_pair(sAl, am0, af * 2, l0, l1);
            split2(pa1.x, pa1.y, h0, l0);
            split2(pa1.z, pa1.w, h1, l1);
            sts_pair(sAh, am1, af * 2, h0, h1);
            sts_pair(sAl, am1, af * 2, l0, l1);
            sts_pair(sBh, wns, wpart * 4 + 0, pwh.x, pwh.y);
            sts_pair(sBh, wns, wpart * 4 + 2, pwh.z, pwh.w);
            sts_pair(sBl, wns, wpart * 4 + 0, pwl.x, pwl.y);
            sts_pair(sBl, wns, wpart * 4 + 2, pwl.z, pwl.w);
        }
        __syncthreads();

        if (kt + 1 < KT) {
            int k0 = (kt + 1) * 16;
            int gm0 = bm + am0, gm1 = bm + am1;
            pa0 = (gm0 < M) ? *(const float4*)&A[(size_t)gm0 * lda + k0 + af * 4] : make_float4(0,0,0,0);
            pa1 = (gm1 < M) ? *(const float4*)&A[(size_t)gm1 * lda + k0 + af * 4] : make_float4(0,0,0,0);
            size_t off = (size_t)(bn + wns) * wstride + (k0 >> 1) + wpart * 4;
            pwh = *(const uint4*)&Wh[off];
            pwl = *(const uint4*)&Wl[off];
        }

        uint32_t ah[2][4], al[2][4];
        #pragma unroll
        for (int mt = 0; mt < 2; mt++) {
            int r0 = wm + mt * 16 + g;
            ah[mt][0] = lds_sw(sAh, r0,     tig);
            ah[mt][1] = lds_sw(sAh, r0 + 8, tig);
            ah[mt][2] = lds_sw(sAh, r0,     tig + 4);
            ah[mt][3] = lds_sw(sAh, r0 + 8, tig + 4);
            al[mt][0] = lds_sw(sAl, r0,     tig);
            al[mt][1] = lds_sw(sAl, r0 + 8, tig);
            al[mt][2] = lds_sw(sAl, r0,     tig + 4);
            al[mt][3] = lds_sw(sAl, r0 + 8, tig + 4);
        }
        #pragma unroll
        for (int nt = 0; nt < 8; nt++) {
            int n = wn + nt * 8 + g;
            uint32_t bh[2], bl[2];
            bh[0] = lds_sw(sBh, n, tig);
            bh[1] = lds_sw(sBh, n, tig + 4);
            bl[0] = lds_sw(sBl, n, tig);
            bl[1] = lds_sw(sBl, n, tig + 4);
            #pragma unroll
            for (int mt = 0; mt < 2; mt++) {
                mma_bf16(acc[mt][nt], ah[mt], bh);
                mma_bf16(acc[mt][nt], al[mt], bh);
                mma_bf16(acc[mt][nt], ah[mt], bl);
            }
        }
        __syncthreads();
    }

    #pragma unroll
    for (int mt = 0; mt < 2; mt++) {
        #pragma unroll
        for (int half = 0; half < 2; half++) {
            int r = bm + wm + mt * 16 + g + half * 8;
            if (r >= M) continue;
            int s = 0, d = 0;
            if (EPI == 2) { s = src[r]; d = dst[r]; }
            #pragma unroll
            for (int nt = 0; nt < 8; nt++) {
                int col0 = bn + wn + nt * 8 + tig * 2;
                float v0 = acc[mt][nt][half * 2 + 0];
                float v1 = acc[mt][nt][half * 2 + 1];
                if (EPI == 2) {
                    v0 = fmaxf(v0 + bias[col0], 0.f);
                    v1 = fmaxf(v1 + bias[col0 + 1], 0.f);
                    red2(&g_xout[(size_t)s * 128 + col0], v0, v1);
                    red2(&g_xin [(size_t)d * 128 + col0], v0, v1);
                } else if (EPI == 1) {
                    *(__half2*)&((__half*)Cv)[(size_t)r * ldc + col0] =
                        __floats2half2_rn(v0, v1);
                } else {
                    *(float2*)&((float*)Cv)[(size_t)r * ldc + col0] = make_float2(v0, v1);
                }
            }
        }
    }
}

// ---------------------------------------------------------------------------
// Pack weights into bf16 hi/lo uint32, n-major [n][kpad/2]. One launch.
// ---------------------------------------------------------------------------
__global__ void k_pack(const float* __restrict__ g1wl, const float* __restrict__ g1wr,
                       const float* __restrict__ g1we, const float* __restrict__ g2we,
                       const float* __restrict__ c1w,  const float* __restrict__ g2wl,
                       const float* __restrict__ g2wr, const float* __restrict__ epw,
                       const float* __restrict__ c2w)
{
    const float* W; int K, N, n0, kpad; uint32_t *dh, *dl;
    switch (blockIdx.y) {
        case 0: W = g1wl;           K = 258; N = 256; n0 = 0;   kpad = 272; dh = wp_W1h; dl = wp_W1l; break;
        case 1: W = g1wr;           K = 258; N = 256; n0 = 256; kpad = 272; dh = wp_W1h; dl = wp_W1l; break;
        case 2: W = g1we;           K = 64;  N = 256; n0 = 0;   kpad = 64;  dh = wp_Weh; dl = wp_Wel; break;
        case 3: W = g2we;           K = 64;  N = 128; n0 = 256; kpad = 64;  dh = wp_Weh; dl = wp_Wel; break;
        case 4: W = c1w + 256*128;  K = 64;  N = 128; n0 = 384; kpad = 64;  dh = wp_Weh; dl = wp_Wel; break;
        case 5: W = g2wl;           K = 128; N = 128; n0 = 0;   kpad = 128; dh = wp_W2h; dl = wp_W2l; break;
        case 6: W = g2wr;           K = 128; N = 128; n0 = 128; kpad = 128; dh = wp_W2h; dl = wp_W2l; break;
        case 7: W = c1w;            K = 128; N = 128; n0 = 0;   kpad = 128; dh = wp_ABh; dl = wp_ABl; break;
        case 8: W = c1w + 128*128;  K = 128; N = 128; n0 = 128; kpad = 128; dh = wp_ABh; dl = wp_ABl; break;
        case 9: W = epw;            K = 64;  N = 128; n0 = 0;   kpad = 64;  dh = wp_Ebh; dl = wp_Ebl; break;
        default: W = c2w;           K = 128; N = 64;  n0 = 0;   kpad = 128; dh = wp_C2h; dl = wp_C2l; break;
    }
    int kh = kpad >> 1;
    int total = N * kh;
    for (int i = blockIdx.x * blockDim.x + threadIdx.x; i < total; i += gridDim.x * blockDim.x) {
        int n = i / kh, k2 = i - n * kh, k = k2 * 2;
        float v0 = (k     < K) ? W[(size_t)k * N + n]       : 0.f;
        float v1 = (k + 1 < K) ? W[(size_t)(k + 1) * N + n] : 0.f;
        uint32_t hi, lo; split2(v0, v1, hi, lo);
        dh[(size_t)(n0 + n) * kh + k2] = hi;
        dl[(size_t)(n0 + n) * kh + k2] = lo;
    }
}

// ---------------------------------------------------------------------------
// Degrees + loop_attr sum. 1 warp / edge.
// ---------------------------------------------------------------------------
__global__ void k_deg_loop(const int* __restrict__ src, const int* __restrict__ dst,
                           const float* __restrict__ ea) {
    int warp = (blockIdx.x * 256 + threadIdx.x) >> 5;
    int lane = threadIdx.x & 31;
    if (warp >= E_) return;
    int s = src[warp], d = dst[warp];
    if (lane == 0) atomicAdd(&g_deg_out[s], 1);
    if (lane == 1) atomicAdd(&g_deg_in[d], 1);
    if (lane < 16) {
        float4 a = reinterpret_cast<const float4*>(ea + (size_t)warp * 64)[lane];
        red4(&g_loop[(size_t)d * 64 + lane * 4], a);
    }
}

// ---------------------------------------------------------------------------
// Build xi (stride 272); finalize loop_attr. 1 warp / node, float4 I/O.
// ---------------------------------------------------------------------------
__global__ void k_build_xi(const float* __restrict__ node_stats) {
    int warp = (blockIdx.x * 256 + threadIdx.x) >> 5;
    int lane = threadIdx.x & 31;
    if (warp >= N_) return;
    float io = 1.f / fmaxf((float)g_deg_out[warp], 1.f);
    float ii = 1.f / fmaxf((float)g_deg_in[warp], 1.f);
    float4 o = ((const float4*)(g_xout + (size_t)warp * 128))[lane];
    float4 i4 = ((const float4*)(g_xin  + (size_t)warp * 128))[lane];
    o.x *= io; o.y *= io; o.z *= io; o.w *= io;
    i4.x *= ii; i4.y *= ii; i4.z *= ii; i4.w *= ii;
    float* xi = g_xi + (size_t)warp * 272;
    ((float4*)xi)[lane] = o;
    ((float4*)(xi + 128))[lane] = i4;
    if (lane < 4) {
        float4 p = make_float4(0.f, 0.f, 0.f, 0.f);
        if (lane == 0) { p.x = node_stats[(size_t)warp * 2]; p.y = node_stats[(size_t)warp * 2 + 1]; }
        ((float4*)(xi + 256))[lane] = p;
    }
    if (lane < 16) {
        float4 l4 = ((float4*)(g_loop + (size_t)warp * 64))[lane];
        l4.x *= ii; l4.y *= ii; l4.z *= ii; l4.w *= ii;
        ((float4*)(g_loop + (size_t)warp * 64))[lane] = l4;
    }
}

// ---------------------------------------------------------------------------
// Fused GATv2 attention over REAL edges only (self-loops live in k_node).
// ew is fp16 (streaming); x is fp32 (gathered). 1 warp / edge, grid = E/8.
// ---------------------------------------------------------------------------
template<int H>
__global__ void k_attn(const float* __restrict__ x, int xstr, int xroff,
                       const __half* __restrict__ ewE, int ewstr,
                       const float* __restrict__ att,
                       const int* __restrict__ src, const int* __restrict__ dst,
                       float* __restrict__ den, float* __restrict__ osum)
{
    const int CH = H * 128;
    __shared__ float satt[CH];
    if (threadIdx.x < CH) satt[threadIdx.x] = att[threadIdx.x];
    __syncthreads();
    int warp = (blockIdx.x * 256 + threadIdx.x) >> 5;
    int lane = threadIdx.x & 31;
    int s = src[warp], d = dst[warp];
    const __half* ew = ewE + (size_t)warp * ewstr;
    const float* pl = x + (size_t)s * xstr;
    const float* pr = x + (size_t)d * xstr + xroff;

    float4 xlv[H];
    float lg[H];
    #pragma unroll
    for (int h = 0; h < H; h++) {
        int off = h * 128 + lane * 4;
        float4 l4 = *(const float4*)&pl[off];
        float4 r4 = *(const float4*)&pr[off];
        uint2 eu = *(const uint2*)&ew[off];
        float2 e01 = __half22float2(*(__half2*)&eu.x);
        float2 e23 = __half22float2(*(__half2*)&eu.y);
        float4 a4 = *(const float4*)&satt[off];
        xlv[h] = l4;
        float v0 = l4.x + r4.x + e01.x; v0 = (v0 > 0.f) ? v0 : 0.2f * v0;
        float v1 = l4.y + r4.y + e01.y; v1 = (v1 > 0.f) ? v1 : 0.2f * v1;
        float v2 = l4.z + r4.z + e23.x; v2 = (v2 > 0.f) ? v2 : 0.2f * v2;
        float v3 = l4.w + r4.w + e23.y; v3 = (v3 > 0.f) ? v3 : 0.2f * v3;
        lg[h] = v0 * a4.x + v1 * a4.y + v2 * a4.z + v3 * a4.w;
    }
    #pragma unroll
    for (int h = 0; h < H; h++)
        #pragma unroll
        for (int o = 16; o > 0; o >>= 1)
            lg[h] += __shfl_xor_sync(0xffffffffu, lg[h], o);
    float a[H];
    #pragma unroll
    for (int h = 0; h < H; h++) a[h] = expf(lg[h]);
    if (lane == 0) {
        #pragma unroll
        for (int h = 0; h < H; h++) atomicAdd(&den[(size_t)d * H + h], a[h]);
    }
    #pragma unroll
    for (int h = 0; h < H; h++) {
        float4 v = xlv[h];
        v.x *= a[h]; v.y *= a[h]; v.z *= a[h]; v.w *= a[h];
        red4(&osum[((size_t)d * H + h) * 128 + lane * 4], v);
    }
}

// ---------------------------------------------------------------------------
// Node finalize WITH self-loop absorption (ewL fp32):
//   a_loop = exp(logit(xl[n], xr[n], ewL[n]))
//   den_tot = den + a_loop;  osum_tot = osum + a_loop * xl[n]
// then head mean + bias, layernorm, elu. 1 warp / node.
// ---------------------------------------------------------------------------
template<int H>
__global__ void k_node(const float* __restrict__ osum, const float* __restrict__ den,
                       const float* __restrict__ x, int xstr, int xroff,
                       const float* __restrict__ ewL, int ewLstr,
                       const float* __restrict__ att,
                       const float* __restrict__ bias,
                       const float* __restrict__ lng, const float* __restrict__ lnb,
                       float* __restrict__ out)
{
    const int CH = H * 128;
    __shared__ float satt[CH];
    if (threadIdx.x < CH) satt[threadIdx.x] = att[threadIdx.x];
    __syncthreads();
    int warp = (blockIdx.x * 256 + threadIdx.x) >> 5;
    int lane = threadIdx.x & 31;
    if (warp >= N_) return;
    int n = warp;

    const float* pl = x + (size_t)n * xstr;
    const float* pr = pl + xroff;
    const float* ew = ewL + (size_t)n * ewLstr;
    float xlv[H][4];
    float lg[H];
    #pragma unroll
    for (int h = 0; h < H; h++) {
        lg[h] = 0.f;
        #pragma unroll
        for (int i = 0; i < 4; i++) {
            int c = h * 128 + i * 32 + lane;
            float l = pl[c];
            float v = l + pr[c] + ew[c];
            v = (v > 0.f) ? v : 0.2f * v;
            xlv[h][i] = l;
            lg[h] += v * satt[c];
        }
    }
    #pragma unroll
    for (int h = 0; h < H; h++)
        #pragma unroll
        for (int o = 16; o > 0; o >>= 1)
            lg[h] += __shfl_xor_sync(0xffffffffu, lg[h], o);
    float aL[H], dinv[H];
    #pragma unroll
    for (int h = 0; h < H; h++) {
        aL[h] = expf(lg[h]);
        dinv[h] = 1.f / fmaxf(den[(size_t)n * H + h] + aL[h], 1e-16f);
    }

    float v[4];
    float sum = 0.f;
    #pragma unroll
    for (int i = 0; i < 4; i++) {
        int c = i * 32 + lane;
        float o = 0.f;
        #pragma unroll
        for (int h = 0; h < H; h++)
            o += (osum[((size_t)n * H + h) * 128 + c] + aL[h] * xlv[h][i]) * dinv[h];
        o = o * (1.f / H) + bias[c];
        v[i] = o;
        sum += o;
    }
    #pragma unroll
    for (int o = 16; o > 0; o >>= 1) sum += __shfl_xor_sync(0xffffffffu, sum, o);
    float mu = sum * (1.f / 128.f);
    float var = 0.f;
    #pragma unroll
    for (int i = 0; i < 4; i++) { float t = v[i] - mu; var += t * t; }
    #pragma unroll
    for (int o = 16; o > 0; o >>= 1) var += __shfl_xor_sync(0xffffffffu, var, o);
    var *= (1.f / 128.f);
    float rs = rsqrtf(var + 1e-5f);
    #pragma unroll
    for (int i = 0; i < 4; i++) {
        int c = i * 32 + lane;
        float hn = (v[i] - mu) * rs * lng[c] + lnb[c];
        hn = (hn > 0.f) ? hn : expm1f(hn);
        out[(size_t)n * 128 + c] = hn;
    }
}

// ---------------------------------------------------------------------------
// Fully fused classifier (two MMA stages, no Cea materialization).
// ---------------------------------------------------------------------------
__global__ __launch_bounds__(256, 2)
void k_classifier(const int* __restrict__ src, const int* __restrict__ dst,
                  const float* __restrict__ ea,
                  const uint32_t* __restrict__ W1h, const uint32_t* __restrict__ W1l,
                  const uint32_t* __restrict__ W2h, const uint32_t* __restrict__ W2l,
                  const float* __restrict__ c1b, const float* __restrict__ c2b,
                  const float* __restrict__ c3w, const float* __restrict__ c3b,
                  float* __restrict__ out)
{
    extern __shared__ __align__(16) char smem_raw[];
    uint32_t* sAh = (uint32_t*)smem_raw;        // 128*8
    uint32_t* sAl = sAh + 128*8;                // 128*8
    uint32_t* s2h = sAl + 128*8;                // 128*64
    uint32_t* s2l = s2h + 128*64;               // 128*64
    int*   ssrc   = (int*)(s2l + 128*64);       // 128
    int*   sdst   = ssrc + 128;                 // 128
    float* rowsum = (float*)(sdst + 128);       // 128

    const int bm = blockIdx.x * 128;
    const int tid = threadIdx.x, wid = tid >> 5, lane = tid & 31;
    const int wm = (wid & 3) * 32;
    const int wn = (wid >> 2) * 64;
    const int wn2 = (wid >> 2) * 32;
    const int g = lane >> 2, tig = lane & 3;
    const int am0 = tid >> 2, af = tid & 3;
    const int am1 = 64 + (tid >> 2);

    if (tid < 128) {
        ssrc[tid] = src[bm + tid];
        sdst[tid] = dst[bm + tid];
        rowsum[tid] = 0.f;
    }

    // stage 1: T = ea @ c1w_e
    float acc1[2][8][4] = {};
    for (int kt = 0; kt < 4; kt++) {
        int k0 = kt * 16;
        {
            float4 a0 = *(const float4*)&ea[(size_t)(bm + am0) * 64 + k0 + af * 4];
            float4 a1 = *(const float4*)&ea[(size_t)(bm + am1) * 64 + k0 + af * 4];
            uint32_t h0, l0, h1, l1;
            split2(a0.x, a0.y, h0, l0); split2(a0.z, a0.w, h1, l1);
            sts_pair(sAh, am0, af * 2, h0, h1); sts_pair(sAl, am0, af * 2, l0, l1);
            split2(a1.x, a1.y, h0, l0); split2(a1.z, a1.w, h1, l1);
            sts_pair(sAh, am1, af * 2, h0, h1); sts_pair(sAl, am1, af * 2, l0, l1);
        }
        __syncthreads();

        uint32_t ah[2][4], al[2][4];
        #pragma unroll
        for (int mt = 0; mt < 2; mt++) {
            int r0 = wm + mt * 16 + g;
            ah[mt][0] = lds_sw(sAh, r0,     tig);
            ah[mt][1] = lds_sw(sAh, r0 + 8, tig);
            ah[mt][2] = lds_sw(sAh, r0,     tig + 4);
            ah[mt][3] = lds_sw(sAh, r0 + 8, tig + 4);
            al[mt][0] = lds_sw(sAl, r0,     tig);
            al[mt][1] = lds_sw(sAl, r0 + 8, tig);
            al[mt][2] = lds_sw(sAl, r0,     tig + 4);
            al[mt][3] = lds_sw(sAl, r0 + 8, tig + 4);
        }
        #pragma unroll
        for (int nt = 0; nt < 8; nt++) {
            int n = wn + nt * 8 + g;
            uint32_t bh[2], bl[2];
            bh[0] = __ldg(&W1h[n * 32 + kt * 8 + tig]);
            bh[1] = __ldg(&W1h[n * 32 + kt * 8 + tig + 4]);
            bl[0] = __ldg(&W1l[n * 32 + kt * 8 + tig]);
            bl[1] = __ldg(&W1l[n * 32 + kt * 8 + tig + 4]);
            #pragma unroll
            for (int mt = 0; mt < 2; mt++) {
                mma_bf16(acc1[mt][nt], ah[mt], bh);
                mma_bf16(acc1[mt][nt], al[mt], bh);
                mma_bf16(acc1[mt][nt], ah[mt], bl);
            }
        }
        __syncthreads();
    }

    // epilogue 1
    #pragma unroll
    for (int mt = 0; mt < 2; mt++) {
        #pragma unroll
        for (int half = 0; half < 2; half++) {
            int r = wm + mt * 16 + g + half * 8;
            int s = ssrc[r], d = sdst[r];
            #pragma unroll
            for (int nt = 0; nt < 8; nt++) {
                int col0 = wn + nt * 8 + tig * 2;
                float v0 = acc1[mt][nt][half * 2 + 0]
                         + g_AB[(size_t)s * 256 + col0]
                         + g_AB[(size_t)d * 256 + 128 + col0] + c1b[col0];
                float v1 = acc1[mt][nt][half * 2 + 1]
                         + g_AB[(size_t)s * 256 + col0 + 1]
                         + g_AB[(size_t)d * 256 + 128 + col0 + 1] + c1b[col0 + 1];
                v0 = fmaxf(v0, 0.f); v1 = fmaxf(v1, 0.f);
                uint32_t hi, lo; split2(v0, v1, hi, lo);
                int k2 = col0 >> 1;
                int sw = k2 ^ ((r & 7) << 3);
                s2h[r * 64 + sw] = hi;
                s2l[r * 64 + sw] = lo;
            }
        }
    }
    __syncthreads();

    // stage 2: T @ c2w
    float acc2[2][4][4] = {};
    #pragma unroll
    for (int kt2 = 0; kt2 < 8; kt2++) {
        uint32_t ah[2][4], al[2][4];
        #pragma unroll
        for (int mt = 0; mt < 2; mt++) {
            int r0 = wm + mt * 16 + g;
            int r1 = r0 + 8;
            int x0 = (r0 & 7) << 3, x1 = (r1 & 7) << 3;
            ah[mt][0] = s2h[r0 * 64 + ((kt2 * 8 + tig)     ^ x0)];
            ah[mt][1] = s2h[r1 * 64 + ((kt2 * 8 + tig)     ^ x1)];
            ah[mt][2] = s2h[r0 * 64 + ((kt2 * 8 + tig + 4) ^ x0)];
            ah[mt][3] = s2h[r1 * 64 + ((kt2 * 8 + tig + 4) ^ x1)];
            al[mt][0] = s2l[r0 * 64 + ((kt2 * 8 + tig)     ^ x0)];
            al[mt][1] = s2l[r1 * 64 + ((kt2 * 8 + tig)     ^ x1)];
            al[mt][2] = s2l[r0 * 64 + ((kt2 * 8 + tig + 4) ^ x0)];
            al[mt][3] = s2l[r1 * 64 + ((kt2 * 8 + tig + 4) ^ x1)];
        }
        #pragma unroll
        for (int nt = 0; nt < 4; nt++) {
            int n = wn2 + nt * 8 + g;
            uint32_t bh[2], bl[2];
            bh[0] = __ldg(&W2h[n * 64 + kt2 * 8 + tig]);
            bh[1] = __ldg(&W2h[n * 64 + kt2 * 8 + tig + 4]);
            bl[0] = __ldg(&W2l[n * 64 + kt2 * 8 + tig]);
            bl[1] = __ldg(&W2l[n * 64 + kt2 * 8 + tig + 4]);
            #pragma unroll
            for (int mt = 0; mt < 2; mt++) {
                mma_bf16(acc2[mt][nt], ah[mt], bh);
                mma_bf16(acc2[mt][nt], al[mt], bh);
                mma_bf16(acc2[mt][nt], ah[mt], bl);
            }
        }
    }

    // epilogue 2
    #pragma unroll
    for (int mt = 0; mt < 2; mt++) {
        #pragma unroll
        for (int half = 0; half < 2; half++) {
            int r = wm + mt * 16 + g + half * 8;
            float p = 0.f;
            #pragma unroll
            for (int nt = 0; nt < 4; nt++) {
                int col = wn2 + nt * 8 + tig * 2;
                float t0 = fmaxf(acc2[mt][nt][half * 2 + 0] + c2b[col], 0.f);
                float t1 = fmaxf(acc2[mt][nt][half * 2 + 1] + c2b[col + 1], 0.f);
                p += t0 * c3w[col] + t1 * c3w[col + 1];
            }
            atomicAdd(&rowsum[r], p);
        }
    }
    __syncthreads();
    if (tid < 128) out[bm + tid] = rowsum[tid] + c3b[0];
}

// ---------------------------------------------------------------------------
// Host launch
// ---------------------------------------------------------------------------
static void* sym(const void* s) { void* p = nullptr; cudaGetSymbolAddress(&p, s); return p; }

static inline dim3 ggrid(int M, int N) { return dim3((N + 127) / 128, (M + 127) / 128); }

#define SMEM_CLS ((128*8*2 + 128*64*2) * 4 + 128*4*2 + 128*4)

extern "C" void kernel_launch(void* const* d_in, const int* in_sizes, int n_in,
                              void* d_out, int out_size)
{
    const float* node_stats = (const float*)d_in[1];
    const int*   edge_index = (const int*)  d_in[2];
    const float* edge_attr  = (const float*)d_in[3];
    const float* epw  = (const float*)d_in[4];
    const float* epb  = (const float*)d_in[5];
    const float* g1wl = (const float*)d_in[6];
    const float* g1wr = (const float*)d_in[7];
    const float* g1we = (const float*)d_in[8];
    const float* g1att= (const float*)d_in[9];
    const float* g1b  = (const float*)d_in[10];
    const float* n1g  = (const float*)d_in[11];
    const float* n1b  = (const float*)d_in[12];
    const float* g2wl = (const float*)d_in[13];
    const float* g2wr = (const float*)d_in[14];
    const float* g2we = (const float*)d_in[15];
    const float* g2att= (const float*)d_in[16];
    const float* g2b  = (const float*)d_in[17];
    const float* n2g  = (const float*)d_in[18];
    const float* n2b  = (const float*)d_in[19];
    const float* c1w  = (const float*)d_in[20];
    const float* c1b  = (const float*)d_in[21];
    const float* c2w  = (const float*)d_in[22];
    const float* c2b  = (const float*)d_in[23];
    const float* c3w  = (const float*)d_in[24];
    const float* c3b  = (const float*)d_in[25];

    const int* src = edge_index;
    const int* dst = edge_index + E_;
    float* out = (float*)d_out;

    float*  p_xi   = (float*) sym(g_xi);
    float*  p_loop = (float*) sym(g_loop);
    float*  p_x1   = (float*) sym(g_x1);
    __half* p_ew   = (__half*)sym(g_ewh);
    float*  p_ewL  = (float*) sym(g_ewL);
    float*  p_den1 = (float*) sym(g_den1);
    float*  p_os1  = (float*) sym(g_osum1);
    float*  p_h1   = (float*) sym(g_h1);
    float*  p_x2   = (float*) sym(g_x2);
    float*  p_den2 = (float*) sym(g_den2);
    float*  p_os2  = (float*) sym(g_osum2);
    float*  p_h2   = (float*) sym(g_h2);
    float*  p_AB   = (float*) sym(g_AB);

    const uint32_t* p_W1h = (const uint32_t*)sym(wp_W1h);
    const uint32_t* p_W1l = (const uint32_t*)sym(wp_W1l);
    const uint32_t* p_Weh = (const uint32_t*)sym(wp_Weh);
    const uint32_t* p_Wel = (const uint32_t*)sym(wp_Wel);
    const uint32_t* p_W2h = (const uint32_t*)sym(wp_W2h);
    const uint32_t* p_W2l = (const uint32_t*)sym(wp_W2l);
    const uint32_t* p_ABh = (const uint32_t*)sym(wp_ABh);
    const uint32_t* p_ABl = (const uint32_t*)sym(wp_ABl);
    const uint32_t* p_Ebh = (const uint32_t*)sym(wp_Ebh);
    const uint32_t* p_Ebl = (const uint32_t*)sym(wp_Ebl);
    const uint32_t* p_C2h = (const uint32_t*)sym(wp_C2h);
    const uint32_t* p_C2l = (const uint32_t*)sym(wp_C2l);

    static bool attr_set = false;
    if (!attr_set) {
        cudaFuncSetAttribute(k_classifier, cudaFuncAttributeMaxDynamicSharedMemorySize, SMEM_CLS);
        attr_set = true;
    }

    // ---- zero accumulators ----
    cudaMemsetAsync(sym(g_deg_out), 0, (size_t)N_ * 4);
    cudaMemsetAsync(sym(g_deg_in),  0, (size_t)N_ * 4);
    cudaMemsetAsync(sym(g_xout),    0, (size_t)N_ * 128 * 4);
    cudaMemsetAsync(sym(g_xin),     0, (size_t)N_ * 128 * 4);
    cudaMemsetAsync(p_loop,         0, (size_t)N_ * 64 * 4);
    cudaMemsetAsync(p_den1,         0, (size_t)N_ * 2 * 4);
    cudaMemsetAsync(p_os1,          0, (size_t)N_ * 256 * 4);
    cudaMemsetAsync(p_den2,         0, (size_t)N_ * 4);
    cudaMemsetAsync(p_os2,          0, (size_t)N_ * 128 * 4);

    // ---- weight packing ----
    k_pack<<<dim3(144, 11), 256>>>(g1wl, g1wr, g1we, g2we, c1w, g2wl, g2wr, epw, c2w);

    // ---- phase 1: degrees, loop sums, emb GEMM fused with scatter ----
    k_deg_loop<<<(E_ + 7) / 8, 256>>>(src, dst, edge_attr);
    gemm_pk<2><<<ggrid(E_, 128), 256>>>(edge_attr, p_Ebh, p_Ebl, epb, nullptr,
                                        E_, 128, 64, 64, 0, src, dst);
    k_build_xi<<<(N_ + 7) / 8, 256>>>(node_stats);

    // ---- combined GEMMs (ew in fp16, rest fp32) ----
    gemm_pk<0><<<ggrid(N_, 512), 256>>>(p_xi, p_W1h, p_W1l, nullptr, p_x1,
                                        N_, 512, 272, 272, 512, nullptr, nullptr);
    gemm_pk<1><<<ggrid(E_, 384), 256>>>(edge_attr, p_Weh, p_Wel, nullptr, p_ew,
                                        E_, 384, 64, 64, 384, nullptr, nullptr);
    gemm_pk<0><<<ggrid(N_, 384), 256>>>(p_loop, p_Weh, p_Wel, nullptr, p_ewL,
                                        N_, 384, 64, 64, 384, nullptr, nullptr);

    // ---- GAT layer 1 (heads=2) ----
    k_attn<2><<<E_ / 8, 256>>>(p_x1, 512, 256, p_ew, 384, g1att, src, dst, p_den1, p_os1);
    k_node<2><<<(N_ + 7) / 8, 256>>>(p_os1, p_den1, p_x1, 512, 256, p_ewL, 384,
                                     g1att, g1b, n1g, n1b, p_h1);

    // ---- GAT layer 2 (heads=1) ----
    gemm_pk<0><<<ggrid(N_, 256), 256>>>(p_h1, p_W2h, p_W2l, nullptr, p_x2,
                                        N_, 256, 128, 128, 256, nullptr, nullptr);
    k_attn<1><<<E_ / 8, 256>>>(p_x2, 256, 128, p_ew + 256, 384, g2att, src, dst, p_den2, p_os2);
    k_node<1><<<(N_ + 7) / 8, 256>>>(p_os2, p_den2, p_x2, 256, 128, p_ewL + 256, 384,
                                     g2att, g2b, n2g, n2b, p_h2);

    // ---- classifier ----
    gemm_pk<0><<<ggrid(N_, 256), 256>>>(p_h2, p_ABh, p_ABl, nullptr, p_AB,
                                        N_, 256, 128, 128, 256, nullptr, nullptr);
    k_classifier<<<E_ / 128, 256, SMEM_CLS>>>(src, dst, edge_attr,
                                              p_Weh + 384 * 32, p_Wel + 384 * 32,
                                              p_C2h, p_C2l,
                                              c1b, c2b, c3w, c3b, out);
}